// round 1
// baseline (speedup 1.0000x reference)
#include <cuda_runtime.h>
#include <math.h>

// Problem constants
#define B_  8
#define T_  512
#define D_  512
#define H_  8
#define FF_ 2048
#define L_  6
#define CS_ 16
#define LC_ 4
#define DK_ 64
#define NCHUNK_ (T_ / CS_)          // 32
#define WMAX_ ((LC_ + 1) * CS_)     // 80

// ---------------- scratch (device globals; no allocation) ----------------
__device__ float g_x [B_*T_*D_];
__device__ float g_h [B_*T_*D_];
__device__ float g_q [B_*T_*D_];
__device__ float g_k [B_*T_*D_];
__device__ float g_v [B_*T_*D_];
__device__ float g_p [T_*D_];
__device__ float g_o [B_*T_*D_];
__device__ float g_ff[B_*T_*FF_];

// ---------------- elementwise scale: x = xs * sqrt(D) ----------------
__global__ void scale_kernel(const float* __restrict__ xs, float s) {
    int i = blockIdx.x * blockDim.x + threadIdx.x;
    g_x[i] = xs[i] * s;
}

// ---------------- LayerNorm over D=512, one block per row ----------------
__global__ void ln_kernel(const float* __restrict__ in, float* __restrict__ out,
                          const float* __restrict__ gam, const float* __restrict__ bet) {
    int row = blockIdx.x;
    int tid = threadIdx.x;                 // 256 threads
    const float* x = in + (size_t)row * D_;
    float v0 = x[tid], v1 = x[tid + 256];
    float s = v0 + v1, ss = v0 * v0 + v1 * v1;
    int lane = tid & 31, warp = tid >> 5;
    #pragma unroll
    for (int off = 16; off; off >>= 1) {
        s  += __shfl_xor_sync(0xffffffffu, s,  off);
        ss += __shfl_xor_sync(0xffffffffu, ss, off);
    }
    __shared__ float sh_s[8], sh_ss[8];
    if (lane == 0) { sh_s[warp] = s; sh_ss[warp] = ss; }
    __syncthreads();
    if (warp == 0) {
        float a = (lane < 8) ? sh_s[lane]  : 0.0f;
        float b = (lane < 8) ? sh_ss[lane] : 0.0f;
        #pragma unroll
        for (int off = 4; off; off >>= 1) {
            a += __shfl_xor_sync(0xffffffffu, a, off);
            b += __shfl_xor_sync(0xffffffffu, b, off);
        }
        if (lane == 0) { sh_s[0] = a; sh_ss[0] = b; }
    }
    __syncthreads();
    float mean = sh_s[0] * (1.0f / D_);
    float var  = sh_ss[0] * (1.0f / D_) - mean * mean;
    float inv  = rsqrtf(var + 1e-5f);
    float* y = out + (size_t)row * D_;
    y[tid]       = (v0 - mean) * inv * gam[tid]       + bet[tid];
    y[tid + 256] = (v1 - mean) * inv * gam[tid + 256] + bet[tid + 256];
}

// ---------------- Tiled SGEMM: C = A[MxK] @ W[KxN] (+bias)(+residual)(relu) ----
// BM=BN=64, BK=16, 256 threads, 4x4 per thread. All dims multiples of 64/16.
__global__ void gemm_kernel(const float* __restrict__ A, const float* __restrict__ W,
                            const float* __restrict__ bias, const float* __restrict__ res,
                            float* __restrict__ C, int M, int N, int K, int relu) {
    __shared__ float As[64][17];   // padded to dodge bank conflicts
    __shared__ float Bs[16][64];
    int tid = threadIdx.x;
    int tx = tid & 15, ty = tid >> 4;
    int rowBase = blockIdx.y * 64, colBase = blockIdx.x * 64;

    int ar = tid >> 2;            // 0..63
    int ac = (tid & 3) * 4;       // 0,4,8,12
    int br = tid >> 4;            // 0..15
    int bc = (tid & 15) * 4;      // 0..60

    float acc[4][4] = {};
    for (int k0 = 0; k0 < K; k0 += 16) {
        float4 av = *(const float4*)(A + (size_t)(rowBase + ar) * K + k0 + ac);
        As[ar][ac + 0] = av.x; As[ar][ac + 1] = av.y;
        As[ar][ac + 2] = av.z; As[ar][ac + 3] = av.w;
        float4 bv = *(const float4*)(W + (size_t)(k0 + br) * N + colBase + bc);
        *(float4*)&Bs[br][bc] = bv;
        __syncthreads();
        #pragma unroll
        for (int kk = 0; kk < 16; kk++) {
            float a0 = As[ty * 4 + 0][kk];
            float a1 = As[ty * 4 + 1][kk];
            float a2 = As[ty * 4 + 2][kk];
            float a3 = As[ty * 4 + 3][kk];
            float4 b4 = *(const float4*)&Bs[kk][tx * 4];
            acc[0][0] += a0 * b4.x; acc[0][1] += a0 * b4.y; acc[0][2] += a0 * b4.z; acc[0][3] += a0 * b4.w;
            acc[1][0] += a1 * b4.x; acc[1][1] += a1 * b4.y; acc[1][2] += a1 * b4.z; acc[1][3] += a1 * b4.w;
            acc[2][0] += a2 * b4.x; acc[2][1] += a2 * b4.y; acc[2][2] += a2 * b4.z; acc[2][3] += a2 * b4.w;
            acc[3][0] += a3 * b4.x; acc[3][1] += a3 * b4.y; acc[3][2] += a3 * b4.z; acc[3][3] += a3 * b4.w;
        }
        __syncthreads();
    }
    #pragma unroll
    for (int i = 0; i < 4; i++) {
        int r = rowBase + ty * 4 + i;
        int c = colBase + tx * 4;
        float4 o;
        float b0 = bias ? bias[c + 0] : 0.0f;
        float b1 = bias ? bias[c + 1] : 0.0f;
        float b2 = bias ? bias[c + 2] : 0.0f;
        float b3 = bias ? bias[c + 3] : 0.0f;
        o.x = acc[i][0] + b0; o.y = acc[i][1] + b1;
        o.z = acc[i][2] + b2; o.w = acc[i][3] + b3;
        if (res) {
            const float4 rv = *(const float4*)(res + (size_t)r * N + c);
            o.x += rv.x; o.y += rv.y; o.z += rv.z; o.w += rv.w;
        }
        if (relu) {
            o.x = fmaxf(o.x, 0.0f); o.y = fmaxf(o.y, 0.0f);
            o.z = fmaxf(o.z, 0.0f); o.w = fmaxf(o.w, 0.0f);
        }
        *(float4*)(C + (size_t)r * N + c) = o;
    }
}

// ---------------- Chunked local attention ----------------
// grid = (NCHUNK, H, B); 16 queries per chunk share key window [s0, s1).
__global__ void attn_kernel(const float* __restrict__ q, const float* __restrict__ k,
                            const float* __restrict__ v, const float* __restrict__ p,
                            const float* __restrict__ pbu, const float* __restrict__ pbv,
                            float* __restrict__ o) {
    int ci = blockIdx.x, h = blockIdx.y, b = blockIdx.z;
    int s0 = max((ci - LC_) * CS_, 0);
    int s1 = (ci + 1) * CS_;
    int W = s1 - s0;
    int t0 = ci * CS_;
    int tid = threadIdx.x;                    // 256 threads

    extern __shared__ float sm[];
    float* Ks = sm;                           // WMAX*64
    float* Ps = Ks + WMAX_ * 64;              // WMAX*64
    float* Vs = Ps + WMAX_ * 64;              // WMAX*64
    float* QU = Vs + WMAX_ * 64;              // 16*64
    float* QV = QU + 16 * 64;                 // 16*64
    float* SC = QV + 16 * 64;                 // 16*WMAX

    for (int idx = tid; idx < W * 64; idx += 256) {
        int s = idx >> 6, d = idx & 63;
        int gi = (((b * T_) + s0 + s) * H_ + h) * DK_ + d;
        Ks[idx] = k[gi];
        Vs[idx] = v[gi];
        Ps[idx] = p[(s0 + s) * D_ + h * DK_ + d];
    }
    for (int idx = tid; idx < 16 * 64; idx += 256) {
        int qi = idx >> 6, d = idx & 63;
        float qv_ = q[(((b * T_) + t0 + qi) * H_ + h) * DK_ + d];
        QU[idx] = qv_ + pbu[h * DK_ + d];
        QV[idx] = qv_ + pbv[h * DK_ + d];
    }
    __syncthreads();

    const float scale = 0.125f;  // 1/sqrt(64)
    for (int idx = tid; idx < 16 * W; idx += 256) {
        int qi = idx / W, s = idx - qi * W;
        float acc = 0.0f;
        #pragma unroll 8
        for (int d = 0; d < 64; d++)
            acc += QU[qi * 64 + d] * Ks[s * 64 + d] + QV[qi * 64 + d] * Ps[s * 64 + d];
        SC[qi * WMAX_ + s] = acc * scale;
    }
    __syncthreads();

    int warp = tid >> 5, lane = tid & 31;
    for (int qi = warp; qi < 16; qi += 8) {
        float m = -1e30f;
        for (int s = lane; s < W; s += 32) m = fmaxf(m, SC[qi * WMAX_ + s]);
        #pragma unroll
        for (int off = 16; off; off >>= 1) m = fmaxf(m, __shfl_xor_sync(0xffffffffu, m, off));
        float sum = 0.0f;
        for (int s = lane; s < W; s += 32) {
            float e = expf(SC[qi * WMAX_ + s] - m);
            SC[qi * WMAX_ + s] = e;
            sum += e;
        }
        #pragma unroll
        for (int off = 16; off; off >>= 1) sum += __shfl_xor_sync(0xffffffffu, sum, off);
        float inv = 1.0f / sum;
        for (int s = lane; s < W; s += 32) SC[qi * WMAX_ + s] *= inv;
    }
    __syncthreads();

    for (int idx = tid; idx < 16 * 64; idx += 256) {
        int qi = idx >> 6, d = idx & 63;
        float acc = 0.0f;
        for (int s = 0; s < W; s++) acc += SC[qi * WMAX_ + s] * Vs[s * 64 + d];
        // write in [B,T,D] layout: o[b, t0+qi, h*64+d]
        o[((b * T_) + t0 + qi) * D_ + h * DK_ + d] = acc;
    }
}

static const int ATTN_SMEM = (WMAX_ * 64 * 3 + 16 * 64 * 2 + 16 * WMAX_) * (int)sizeof(float); // 74752

extern "C" void kernel_launch(void* const* d_in, const int* in_sizes, int n_in,
                              void* d_out, int out_size) {
    (void)in_sizes; (void)n_in; (void)out_size;
    const float* xs    = (const float*)d_in[0];
    const float* pos   = (const float*)d_in[1];
    // d_in[2] = mask: unused (window computed analytically)
    const float* Wq    = (const float*)d_in[3];
    const float* bq    = (const float*)d_in[4];
    const float* Wk    = (const float*)d_in[5];
    const float* bk    = (const float*)d_in[6];
    const float* Wv    = (const float*)d_in[7];
    const float* bv    = (const float*)d_in[8];
    const float* Wo    = (const float*)d_in[9];
    const float* bo    = (const float*)d_in[10];
    const float* Wp    = (const float*)d_in[11];
    const float* pbu   = (const float*)d_in[12];
    const float* pbv   = (const float*)d_in[13];
    const float* ln1s  = (const float*)d_in[14];
    const float* ln1b  = (const float*)d_in[15];
    const float* ln2s  = (const float*)d_in[16];
    const float* ln2b  = (const float*)d_in[17];
    const float* W1    = (const float*)d_in[18];
    const float* b1    = (const float*)d_in[19];
    const float* W2    = (const float*)d_in[20];
    const float* b2    = (const float*)d_in[21];
    const float* lnfs  = (const float*)d_in[22];
    const float* lnfb  = (const float*)d_in[23];

    cudaFuncSetAttribute(attn_kernel, cudaFuncAttributeMaxDynamicSharedMemorySize, ATTN_SMEM);

    void *px_, *ph_, *pq_, *pk_, *pv_, *pp_, *po_, *pff_;
    cudaGetSymbolAddress(&px_,  g_x);
    cudaGetSymbolAddress(&ph_,  g_h);
    cudaGetSymbolAddress(&pq_,  g_q);
    cudaGetSymbolAddress(&pk_,  g_k);
    cudaGetSymbolAddress(&pv_,  g_v);
    cudaGetSymbolAddress(&pp_,  g_p);
    cudaGetSymbolAddress(&po_,  g_o);
    cudaGetSymbolAddress(&pff_, g_ff);
    float* px  = (float*)px_;
    float* ph  = (float*)ph_;
    float* pq  = (float*)pq_;
    float* pk  = (float*)pk_;
    float* pv  = (float*)pv_;
    float* pp  = (float*)pp_;
    float* po  = (float*)po_;
    float* pff = (float*)pff_;

    const int M = B_ * T_;  // 4096

    // x = xs * sqrt(D)
    scale_kernel<<<(B_*T_*D_) / 256, 256>>>(xs, sqrtf((float)D_));

    for (int l = 0; l < L_; l++) {
        const float* Wq_l  = Wq  + (size_t)l * D_ * D_;
        const float* Wk_l  = Wk  + (size_t)l * D_ * D_;
        const float* Wv_l  = Wv  + (size_t)l * D_ * D_;
        const float* Wo_l  = Wo  + (size_t)l * D_ * D_;
        const float* Wp_l  = Wp  + (size_t)l * D_ * D_;
        const float* W1_l  = W1  + (size_t)l * D_ * FF_;
        const float* W2_l  = W2  + (size_t)l * FF_ * D_;

        // h = LN1(x)
        ln_kernel<<<M, 256>>>(px, ph, ln1s + l * D_, ln1b + l * D_);

        // q,k,v = h @ W{q,k,v} + b
        gemm_kernel<<<dim3(D_/64, M/64), 256>>>(ph, Wq_l, bq + l*D_, nullptr, pq, M, D_, D_, 0);
        gemm_kernel<<<dim3(D_/64, M/64), 256>>>(ph, Wk_l, bk + l*D_, nullptr, pk, M, D_, D_, 0);
        gemm_kernel<<<dim3(D_/64, M/64), 256>>>(ph, Wv_l, bv + l*D_, nullptr, pv, M, D_, D_, 0);

        // p = pos_emb @ Wp
        gemm_kernel<<<dim3(D_/64, T_/64), 256>>>(pos, Wp_l, nullptr, nullptr, pp, T_, D_, D_, 0);

        // attention (chunked local, writes [B,T,D] layout)
        attn_kernel<<<dim3(NCHUNK_, H_, B_), 256, ATTN_SMEM>>>(
            pq, pk, pv, pp, pbu + l * H_ * DK_, pbv + l * H_ * DK_, po);

        // x = x + o @ Wo + bo
        gemm_kernel<<<dim3(D_/64, M/64), 256>>>(po, Wo_l, bo + l*D_, px, px, M, D_, D_, 0);

        // h = LN2(x)
        ln_kernel<<<M, 256>>>(px, ph, ln2s + l * D_, ln2b + l * D_);

        // ff = relu(h @ W1 + b1)
        gemm_kernel<<<dim3(FF_/64, M/64), 256>>>(ph, W1_l, b1 + l*FF_, nullptr, pff, M, FF_, D_, 1);

        // x = x + ff @ W2 + b2
        gemm_kernel<<<dim3(D_/64, M/64), 256>>>(pff, W2_l, b2 + l*D_, px, px, M, D_, FF_, 0);
    }

    // out = LNf(x)
    ln_kernel<<<M, 256>>>(px, (float*)d_out, lnfs, lnfb);
}

// round 3
// speedup vs baseline: 1.7555x; 1.7555x over previous
#include <cuda_runtime.h>
#include <cuda_fp16.h>
#include <math.h>
#include <stdint.h>

// Problem constants
#define B_  8
#define T_  512
#define D_  512
#define H_  8
#define FF_ 2048
#define L_  6
#define CS_ 16
#define LC_ 4
#define DK_ 64
#define NCHUNK_ (T_ / CS_)          // 32
#define WMAX_ ((LC_ + 1) * CS_)     // 80

// ---------------- scratch (device globals; no allocation) ----------------
__device__ float g_x [B_*T_*D_];
__device__ float g_q [B_*T_*D_];
__device__ float g_k [B_*T_*D_];
__device__ float g_v [B_*T_*D_];
__device__ float g_p [T_*D_];

__device__ __half g_hh [B_*T_*D_],  g_hl [B_*T_*D_];   // LN output hi/lo
__device__ __half g_oh [B_*T_*D_],  g_ol [B_*T_*D_];   // attention out hi/lo
__device__ __half g_ffh[B_*T_*FF_], g_ffl[B_*T_*FF_];  // FF1 out hi/lo
__device__ __half g_posh[T_*D_],    g_posl[T_*D_];     // pos_emb hi/lo

// transposed + split weights: Wt[n][k]
__device__ __half g_wqh[L_*D_*D_],  g_wql[L_*D_*D_];
__device__ __half g_wkh[L_*D_*D_],  g_wkl[L_*D_*D_];
__device__ __half g_wvh[L_*D_*D_],  g_wvl[L_*D_*D_];
__device__ __half g_woh[L_*D_*D_],  g_wol[L_*D_*D_];
__device__ __half g_wph[L_*D_*D_],  g_wpl[L_*D_*D_];
__device__ __half g_w1h[L_*D_*FF_], g_w1l[L_*D_*FF_];
__device__ __half g_w2h[L_*FF_*D_], g_w2l[L_*FF_*D_];

// ---------------- PTX helpers (family-portable: sm_80+ ISA only) ----------
__device__ __forceinline__ uint32_t s2u(const void* p) {
    uint32_t a;
    asm("{ .reg .u64 t; cvta.to.shared.u64 t, %1; cvt.u32.u64 %0, t; }" : "=r"(a) : "l"(p));
    return a;
}

#define CPA16(sa, g) \
    asm volatile("cp.async.cg.shared.global [%0], [%1], 16;" :: "r"(sa), "l"(g) : "memory")
#define CPCOMMIT() asm volatile("cp.async.commit_group;" ::: "memory")
#define CPWAIT(n)  asm volatile("cp.async.wait_group %0;" :: "n"(n) : "memory")

#define LDSM4(d0, d1, d2, d3, a) \
    asm volatile("ldmatrix.sync.aligned.m8n8.x4.shared.b16 {%0,%1,%2,%3}, [%4];" \
        : "=r"(d0), "=r"(d1), "=r"(d2), "=r"(d3) : "r"(a))

#define MMA16816(c, a, b0, b1) \
    asm volatile("mma.sync.aligned.m16n8k16.row.col.f32.f16.f16.f32 " \
        "{%0,%1,%2,%3}, {%4,%5,%6,%7}, {%8,%9}, {%0,%1,%2,%3};" \
        : "+f"((c)[0]), "+f"((c)[1]), "+f"((c)[2]), "+f"((c)[3]) \
        : "r"((a)[0]), "r"((a)[1]), "r"((a)[2]), "r"((a)[3]), "r"(b0), "r"(b1))

__device__ __forceinline__ void split_h(float v, __half& hi, __half& lo) {
    hi = __float2half_rn(v);
    lo = __float2half_rn(v - __half2float(hi));
}

// ---------------- elementwise scale: x = xs * sqrt(D) ----------------
__global__ void scale_kernel(const float* __restrict__ xs, float s) {
    int i = blockIdx.x * blockDim.x + threadIdx.x;
    g_x[i] = xs[i] * s;
}

// ---------------- pos_emb split: fp32 -> fp16 hi/lo ----------------
__global__ void posconv_kernel(const float* __restrict__ pos) {
    int i = blockIdx.x * blockDim.x + threadIdx.x;
    __half h, l;
    split_h(pos[i], h, l);
    g_posh[i] = h; g_posl[i] = l;
}

// ---------------- weight transpose + split: W[K][N] -> Wt_hi/lo[N][K] ------
// grid (N/32, K/32, L), block (32, 8)
__global__ void wtrans_kernel(const float* __restrict__ W,
                              __half* __restrict__ Th,
                              __half* __restrict__ Tl, int K, int N) {
    __shared__ float sm[32][33];
    size_t loff = (size_t)blockIdx.z * K * N;
    const float* Wl = W + loff;
    __half* Thl = Th + loff;
    __half* Tll = Tl + loff;
    int n0 = blockIdx.x * 32, k0 = blockIdx.y * 32;
    int tx = threadIdx.x, ty = threadIdx.y;
    #pragma unroll
    for (int j = 0; j < 4; j++)
        sm[ty + j * 8][tx] = Wl[(size_t)(k0 + ty + j * 8) * N + n0 + tx];
    __syncthreads();
    #pragma unroll
    for (int j = 0; j < 4; j++) {
        int n = ty + j * 8;
        float v = sm[tx][n];
        __half h, l;
        split_h(v, h, l);
        size_t o = (size_t)(n0 + n) * K + k0 + tx;
        Thl[o] = h; Tll[o] = l;
    }
}

// ---------------- LayerNorm ----------------
__device__ __forceinline__ void ln_stats(const float* x, int tid, float& v0, float& v1,
                                         float& mean, float& inv, float* sh_s, float* sh_ss) {
    v0 = x[tid]; v1 = x[tid + 256];
    float s = v0 + v1, ss = v0 * v0 + v1 * v1;
    int lane = tid & 31, warp = tid >> 5;
    #pragma unroll
    for (int off = 16; off; off >>= 1) {
        s  += __shfl_xor_sync(0xffffffffu, s,  off);
        ss += __shfl_xor_sync(0xffffffffu, ss, off);
    }
    if (lane == 0) { sh_s[warp] = s; sh_ss[warp] = ss; }
    __syncthreads();
    if (warp == 0) {
        float a = (lane < 8) ? sh_s[lane]  : 0.0f;
        float b = (lane < 8) ? sh_ss[lane] : 0.0f;
        #pragma unroll
        for (int off = 4; off; off >>= 1) {
            a += __shfl_xor_sync(0xffffffffu, a, off);
            b += __shfl_xor_sync(0xffffffffu, b, off);
        }
        if (lane == 0) { sh_s[0] = a; sh_ss[0] = b; }
    }
    __syncthreads();
    mean = sh_s[0] * (1.0f / D_);
    float var = sh_ss[0] * (1.0f / D_) - mean * mean;
    inv = rsqrtf(var + 1e-5f);
}

__global__ void ln_kernel(const float* __restrict__ in, float* __restrict__ out,
                          const float* __restrict__ gam, const float* __restrict__ bet) {
    __shared__ float sh_s[8], sh_ss[8];
    int row = blockIdx.x, tid = threadIdx.x;
    const float* x = in + (size_t)row * D_;
    float v0, v1, mean, inv;
    ln_stats(x, tid, v0, v1, mean, inv, sh_s, sh_ss);
    float* y = out + (size_t)row * D_;
    y[tid]       = (v0 - mean) * inv * gam[tid]       + bet[tid];
    y[tid + 256] = (v1 - mean) * inv * gam[tid + 256] + bet[tid + 256];
}

// LayerNorm writing fp16 hi/lo split
__global__ void ln_h3_kernel(const float* __restrict__ in,
                             __half* __restrict__ oh, __half* __restrict__ ol,
                             const float* __restrict__ gam, const float* __restrict__ bet) {
    __shared__ float sh_s[8], sh_ss[8];
    int row = blockIdx.x, tid = threadIdx.x;
    const float* x = in + (size_t)row * D_;
    float v0, v1, mean, inv;
    ln_stats(x, tid, v0, v1, mean, inv, sh_s, sh_ss);
    float y0 = (v0 - mean) * inv * gam[tid]       + bet[tid];
    float y1 = (v1 - mean) * inv * gam[tid + 256] + bet[tid + 256];
    __half h, l;
    size_t o = (size_t)row * D_ + tid;
    split_h(y0, h, l); oh[o] = h; ol[o] = l;
    split_h(y1, h, l); oh[o + 256] = h; ol[o + 256] = l;
}

// ---------------- HMMA fp16x3 GEMM ----------------
// C[M x N] = A[M x K] @ W[K x N]; A row-major fp16 hi/lo, W pre-transposed
// as Bt[N][K] fp16 hi/lo (k-major -> mma row.col layout).
// Block 128x128x32, 8 warps, warp tile 64x32, cp.async double buffer,
// XOR-swizzled 64B smem rows (conflict-free ldmatrix). fp32 accum.
// Epilogue: +bias, +residual, relu; fp32 and/or fp16 hi/lo outputs.
#define STAGE_BYTES 32768
__global__ void __launch_bounds__(256, 1)
gemm_h3(const __half* __restrict__ Ah, const __half* __restrict__ Al,
        const __half* __restrict__ Bh, const __half* __restrict__ Bl,
        const float* __restrict__ bias, const float* __restrict__ res,
        float* __restrict__ outF,
        __half* __restrict__ outH, __half* __restrict__ outL,
        int N, int K, int relu) {
    extern __shared__ char smem[];
    uint32_t sb = s2u(smem);
    int tid = threadIdx.x, lane = tid & 31, wid = tid >> 5;
    int wm = wid >> 2, wn = wid & 3;
    int rowBase = blockIdx.y * 128, colBase = blockIdx.x * 128;
    int sub = lane & 7, grp = lane >> 3;

    float acc[4][4][4];
    #pragma unroll
    for (int i = 0; i < 4; i++)
        #pragma unroll
        for (int j = 0; j < 4; j++)
            #pragma unroll
            for (int c = 0; c < 4; c++) acc[i][j][c] = 0.0f;

    const int NC = K >> 5;

    // --- stage loader: 512 16B-chunks per operand array ---
    auto load_stage = [&](int c, int buf) {
        uint32_t sbase = sb + buf * STAGE_BYTES;
        int k0 = c << 5;
        #pragma unroll
        for (int i = 0; i < 2; i++) {
            int id  = tid + (i << 8);
            int row = id >> 2, ch = id & 3;
            int phys = ch ^ ((row >> 1) & 3);
            uint32_t so = sbase + row * 64 + phys * 16;
            const __half* gA = Ah + (size_t)(rowBase + row) * K + k0 + ch * 8;
            const __half* gAl = Al + (size_t)(rowBase + row) * K + k0 + ch * 8;
            const __half* gB = Bh + (size_t)(colBase + row) * K + k0 + ch * 8;
            const __half* gBl = Bl + (size_t)(colBase + row) * K + k0 + ch * 8;
            CPA16(so,          gA);
            CPA16(so + 8192u,  gAl);
            CPA16(so + 16384u, gB);
            CPA16(so + 24576u, gBl);
        }
    };

    auto compute = [&](int buf) {
        uint32_t base = sb + buf * STAGE_BYTES;
        #pragma unroll
        for (int ks = 0; ks < 2; ks++) {
            uint32_t ahf[4][4], alf[4][4], bhf[4][2], blf[4][2];
            #pragma unroll
            for (int mi = 0; mi < 4; mi++) {
                int row = wm * 64 + mi * 16 + sub + (grp & 1) * 8;
                int ci = 2 * ks + (grp >> 1);
                uint32_t ad = base + row * 64 + ((ci ^ ((row >> 1) & 3)) * 16);
                LDSM4(ahf[mi][0], ahf[mi][1], ahf[mi][2], ahf[mi][3], ad);
                LDSM4(alf[mi][0], alf[mi][1], alf[mi][2], alf[mi][3], ad + 8192u);
            }
            #pragma unroll
            for (int g = 0; g < 2; g++) {
                int row = wn * 32 + g * 16 + sub + (grp & 1) * 8;
                int ci = 2 * ks + (grp >> 1);
                uint32_t ad = base + 16384u + row * 64 + ((ci ^ ((row >> 1) & 3)) * 16);
                uint32_t r0, r1, r2, r3;
                LDSM4(r0, r1, r2, r3, ad);
                bhf[2*g][0] = r0; bhf[2*g+1][0] = r1; bhf[2*g][1] = r2; bhf[2*g+1][1] = r3;
                LDSM4(r0, r1, r2, r3, ad + 8192u);
                blf[2*g][0] = r0; blf[2*g+1][0] = r1; blf[2*g][1] = r2; blf[2*g+1][1] = r3;
            }
            #pragma unroll
            for (int mi = 0; mi < 4; mi++)
                #pragma unroll
                for (int nj = 0; nj < 4; nj++)
                    MMA16816(acc[mi][nj], ahf[mi], bhf[nj][0], bhf[nj][1]);
            #pragma unroll
            for (int mi = 0; mi < 4; mi++)
                #pragma unroll
                for (int nj = 0; nj < 4; nj++)
                    MMA16816(acc[mi][nj], ahf[mi], blf[nj][0], blf[nj][1]);
            #pragma unroll
            for (int mi = 0; mi < 4; mi++)
                #pragma unroll
                for (int nj = 0; nj < 4; nj++)
                    MMA16816(acc[mi][nj], alf[mi], bhf[nj][0], bhf[nj][1]);
        }
    };

    load_stage(0, 0);
    CPCOMMIT();
    for (int c = 0; c < NC; c++) {
        if (c + 1 < NC) {
            load_stage(c + 1, (c + 1) & 1);
            CPCOMMIT();
            CPWAIT(1);
        } else {
            CPWAIT(0);
        }
        __syncthreads();
        compute(c & 1);
        __syncthreads();
    }

    // --- epilogue ---
    #pragma unroll
    for (int mi = 0; mi < 4; mi++) {
        #pragma unroll
        for (int nj = 0; nj < 4; nj++) {
            int r = rowBase + wm * 64 + mi * 16 + (lane >> 2);
            int c = colBase + wn * 32 + nj * 8 + ((lane & 3) << 1);
            #pragma unroll
            for (int half_ : {0, 1}) {
                int rr = r + half_ * 8;
                float v0 = acc[mi][nj][half_ * 2 + 0];
                float v1 = acc[mi][nj][half_ * 2 + 1];
                if (bias) { v0 += bias[c]; v1 += bias[c + 1]; }
                if (res) {
                    float2 rv = *(const float2*)(res + (size_t)rr * N + c);
                    v0 += rv.x; v1 += rv.y;
                }
                if (relu) { v0 = fmaxf(v0, 0.0f); v1 = fmaxf(v1, 0.0f); }
                if (outF)
                    *(float2*)(outF + (size_t)rr * N + c) = make_float2(v0, v1);
                if (outH) {
                    __half h0, l0, h1, l1;
                    split_h(v0, h0, l0);
                    split_h(v1, h1, l1);
                    *(__half2*)(outH + (size_t)rr * N + c) = __halves2half2(h0, h1);
                    *(__half2*)(outL + (size_t)rr * N + c) = __halves2half2(l0, l1);
                }
            }
        }
    }
}

// ---------------- Chunked local attention (fp16 hi/lo output) --------------
__global__ void attn_kernel(const float* __restrict__ q, const float* __restrict__ k,
                            const float* __restrict__ v, const float* __restrict__ p,
                            const float* __restrict__ pbu, const float* __restrict__ pbv,
                            __half* __restrict__ oh, __half* __restrict__ ol) {
    int ci = blockIdx.x, h = blockIdx.y, b = blockIdx.z;
    int s0 = max((ci - LC_) * CS_, 0);
    int s1 = (ci + 1) * CS_;
    int W = s1 - s0;
    int t0 = ci * CS_;
    int tid = threadIdx.x;                    // 256 threads

    extern __shared__ float sm[];
    float* Ks = sm;
    float* Ps = Ks + WMAX_ * 64;
    float* Vs = Ps + WMAX_ * 64;
    float* QU = Vs + WMAX_ * 64;
    float* QV = QU + 16 * 64;
    float* SC = QV + 16 * 64;

    for (int idx = tid; idx < W * 64; idx += 256) {
        int s = idx >> 6, d = idx & 63;
        int gi = (((b * T_) + s0 + s) * H_ + h) * DK_ + d;
        Ks[idx] = k[gi];
        Vs[idx] = v[gi];
        Ps[idx] = p[(s0 + s) * D_ + h * DK_ + d];
    }
    for (int idx = tid; idx < 16 * 64; idx += 256) {
        int qi = idx >> 6, d = idx & 63;
        float qv_ = q[(((b * T_) + t0 + qi) * H_ + h) * DK_ + d];
        QU[idx] = qv_ + pbu[h * DK_ + d];
        QV[idx] = qv_ + pbv[h * DK_ + d];
    }
    __syncthreads();

    const float scale = 0.125f;
    for (int idx = tid; idx < 16 * W; idx += 256) {
        int qi = idx / W, s = idx - qi * W;
        float acc = 0.0f;
        #pragma unroll 8
        for (int d = 0; d < 64; d++)
            acc += QU[qi * 64 + d] * Ks[s * 64 + d] + QV[qi * 64 + d] * Ps[s * 64 + d];
        SC[qi * WMAX_ + s] = acc * scale;
    }
    __syncthreads();

    int warp = tid >> 5, lane = tid & 31;
    for (int qi = warp; qi < 16; qi += 8) {
        float m = -1e30f;
        for (int s = lane; s < W; s += 32) m = fmaxf(m, SC[qi * WMAX_ + s]);
        #pragma unroll
        for (int off = 16; off; off >>= 1) m = fmaxf(m, __shfl_xor_sync(0xffffffffu, m, off));
        float sum = 0.0f;
        for (int s = lane; s < W; s += 32) {
            float e = expf(SC[qi * WMAX_ + s] - m);
            SC[qi * WMAX_ + s] = e;
            sum += e;
        }
        #pragma unroll
        for (int off = 16; off; off >>= 1) sum += __shfl_xor_sync(0xffffffffu, sum, off);
        float inv = 1.0f / sum;
        for (int s = lane; s < W; s += 32) SC[qi * WMAX_ + s] *= inv;
    }
    __syncthreads();

    for (int idx = tid; idx < 16 * 64; idx += 256) {
        int qi = idx >> 6, d = idx & 63;
        float acc = 0.0f;
        for (int s = 0; s < W; s++) acc += SC[qi * WMAX_ + s] * Vs[s * 64 + d];
        __half hh, ll;
        split_h(acc, hh, ll);
        size_t o = (size_t)((b * T_) + t0 + qi) * D_ + h * DK_ + d;
        oh[o] = hh; ol[o] = ll;
    }
}

static const int ATTN_SMEM = (WMAX_ * 64 * 3 + 16 * 64 * 2 + 16 * WMAX_) * (int)sizeof(float);
static const int GEMM_SMEM = 2 * STAGE_BYTES;   // 65536

extern "C" void kernel_launch(void* const* d_in, const int* in_sizes, int n_in,
                              void* d_out, int out_size) {
    (void)in_sizes; (void)n_in; (void)out_size;
    const float* xs    = (const float*)d_in[0];
    const float* pos   = (const float*)d_in[1];
    // d_in[2] = mask: unused (window computed analytically)
    const float* Wq    = (const float*)d_in[3];
    const float* bq    = (const float*)d_in[4];
    const float* Wk    = (const float*)d_in[5];
    const float* bk    = (const float*)d_in[6];
    const float* Wv    = (const float*)d_in[7];
    const float* bv    = (const float*)d_in[8];
    const float* Wo    = (const float*)d_in[9];
    const float* bo    = (const float*)d_in[10];
    const float* Wp    = (const float*)d_in[11];
    const float* pbu   = (const float*)d_in[12];
    const float* pbv   = (const float*)d_in[13];
    const float* ln1s  = (const float*)d_in[14];
    const float* ln1b  = (const float*)d_in[15];
    const float* ln2s  = (const float*)d_in[16];
    const float* ln2b  = (const float*)d_in[17];
    const float* W1    = (const float*)d_in[18];
    const float* b1    = (const float*)d_in[19];
    const float* W2    = (const float*)d_in[20];
    const float* b2    = (const float*)d_in[21];
    const float* lnfs  = (const float*)d_in[22];
    const float* lnfb  = (const float*)d_in[23];

    cudaFuncSetAttribute(attn_kernel, cudaFuncAttributeMaxDynamicSharedMemorySize, ATTN_SMEM);
    cudaFuncSetAttribute(gemm_h3,     cudaFuncAttributeMaxDynamicSharedMemorySize, GEMM_SMEM);

    // symbol addresses
    void* a;
    #define SYM(p, s) cudaGetSymbolAddress(&a, s); auto* p = (decltype(&s[0]))a;
    SYM(px,   g_x)   SYM(pq, g_q)  SYM(pk, g_k)  SYM(pv, g_v)  SYM(pp, g_p)
    SYM(phh,  g_hh)  SYM(phl, g_hl)
    SYM(poh,  g_oh)  SYM(pol, g_ol)
    SYM(pffh, g_ffh) SYM(pffl, g_ffl)
    SYM(pposh, g_posh) SYM(pposl, g_posl)
    SYM(pwqh, g_wqh) SYM(pwql, g_wql)
    SYM(pwkh, g_wkh) SYM(pwkl, g_wkl)
    SYM(pwvh, g_wvh) SYM(pwvl, g_wvl)
    SYM(pwoh, g_woh) SYM(pwol, g_wol)
    SYM(pwph, g_wph) SYM(pwpl, g_wpl)
    SYM(pw1h, g_w1h) SYM(pw1l, g_w1l)
    SYM(pw2h, g_w2h) SYM(pw2l, g_w2l)
    #undef SYM

    const int M = B_ * T_;  // 4096

    // x = xs * sqrt(D); pos split; weight transpose+split (all layers)
    scale_kernel<<<(B_*T_*D_) / 256, 256>>>(xs, sqrtf((float)D_));
    posconv_kernel<<<(T_*D_) / 256, 256>>>(pos);
    dim3 wtb(32, 8);
    wtrans_kernel<<<dim3(D_/32,  D_/32,  L_), wtb>>>(Wq, pwqh, pwql, D_,  D_);
    wtrans_kernel<<<dim3(D_/32,  D_/32,  L_), wtb>>>(Wk, pwkh, pwkl, D_,  D_);
    wtrans_kernel<<<dim3(D_/32,  D_/32,  L_), wtb>>>(Wv, pwvh, pwvl, D_,  D_);
    wtrans_kernel<<<dim3(D_/32,  D_/32,  L_), wtb>>>(Wo, pwoh, pwol, D_,  D_);
    wtrans_kernel<<<dim3(D_/32,  D_/32,  L_), wtb>>>(Wp, pwph, pwpl, D_,  D_);
    wtrans_kernel<<<dim3(FF_/32, D_/32,  L_), wtb>>>(W1, pw1h, pw1l, D_,  FF_);
    wtrans_kernel<<<dim3(D_/32,  FF_/32, L_), wtb>>>(W2, pw2h, pw2l, FF_, D_);

    for (int l = 0; l < L_; l++) {
        size_t wdd = (size_t)l * D_ * D_;
        size_t wdf = (size_t)l * D_ * FF_;

        // h = LN1(x)  (fp16 hi/lo)
        ln_h3_kernel<<<M, 256>>>(px, phh, phl, ln1s + l * D_, ln1b + l * D_);

        // q,k,v = h @ W{q,k,v} + b   (fp32 out)
        gemm_h3<<<dim3(D_/128, M/128), 256, GEMM_SMEM>>>(phh, phl, pwqh + wdd, pwql + wdd,
            bq + l*D_, nullptr, pq, nullptr, nullptr, D_, D_, 0);
        gemm_h3<<<dim3(D_/128, M/128), 256, GEMM_SMEM>>>(phh, phl, pwkh + wdd, pwkl + wdd,
            bk + l*D_, nullptr, pk, nullptr, nullptr, D_, D_, 0);
        gemm_h3<<<dim3(D_/128, M/128), 256, GEMM_SMEM>>>(phh, phl, pwvh + wdd, pwvl + wdd,
            bv + l*D_, nullptr, pv, nullptr, nullptr, D_, D_, 0);

        // p = pos_emb @ Wp (fp32 out)
        gemm_h3<<<dim3(D_/128, T_/128), 256, GEMM_SMEM>>>(pposh, pposl, pwph + wdd, pwpl + wdd,
            nullptr, nullptr, pp, nullptr, nullptr, D_, D_, 0);

        // attention (chunked local) -> o hi/lo
        attn_kernel<<<dim3(NCHUNK_, H_, B_), 256, ATTN_SMEM>>>(
            pq, pk, pv, pp, pbu + l * H_ * DK_, pbv + l * H_ * DK_, poh, pol);

        // x = x + o @ Wo + bo
        gemm_h3<<<dim3(D_/128, M/128), 256, GEMM_SMEM>>>(poh, pol, pwoh + wdd, pwol + wdd,
            bo + l*D_, px, px, nullptr, nullptr, D_, D_, 0);

        // h2 = LN2(x)  (fp16 hi/lo)
        ln_h3_kernel<<<M, 256>>>(px, phh, phl, ln2s + l * D_, ln2b + l * D_);

        // ff = relu(h2 @ W1 + b1)  (fp16 hi/lo out only)
        gemm_h3<<<dim3(FF_/128, M/128), 256, GEMM_SMEM>>>(phh, phl, pw1h + wdf, pw1l + wdf,
            b1 + l*FF_, nullptr, nullptr, pffh, pffl, FF_, D_, 1);

        // x = x + ff @ W2 + b2
        gemm_h3<<<dim3(D_/128, M/128), 256, GEMM_SMEM>>>(pffh, pffl, pw2h + wdf, pw2l + wdf,
            b2 + l*D_, px, px, nullptr, nullptr, D_, FF_, 0);
    }

    // out = LNf(x)  (fp32)
    ln_kernel<<<M, 256>>>(px, (float*)d_out, lnfs, lnfb);
}

// round 4
// speedup vs baseline: 2.3837x; 1.3578x over previous
#include <cuda_runtime.h>
#include <cuda_fp16.h>
#include <math.h>
#include <stdint.h>

// Problem constants
#define B_  8
#define T_  512
#define D_  512
#define H_  8
#define FF_ 2048
#define L_  6
#define CS_ 16
#define LC_ 4
#define DK_ 64
#define NCHUNK_ (T_ / CS_)          // 32
#define WMAX_ ((LC_ + 1) * CS_)     // 80
#define QKVN_ (3 * D_)              // 1536
#define PALLN_ (L_ * D_)            // 3072

// ---------------- scratch (device globals; no allocation) ----------------
__device__ float g_x   [B_*T_*D_];
__device__ float g_qkv [B_*T_*QKVN_];
__device__ float g_pall[T_*PALLN_];
__device__ float g_bqkv[L_*QKVN_];

__device__ __half g_hh [B_*T_*D_],  g_hl [B_*T_*D_];   // LN output hi/lo
__device__ __half g_oh [B_*T_*D_],  g_ol [B_*T_*D_];   // attention out hi/lo
__device__ __half g_ffh[B_*T_*FF_], g_ffl[B_*T_*FF_];  // FF1 out hi/lo
__device__ __half g_posh[T_*D_],    g_posl[T_*D_];     // pos_emb hi/lo

// transposed + split weights: Wt[n][k]
__device__ __half g_wqkvh[L_*QKVN_*D_], g_wqkvl[L_*QKVN_*D_];
__device__ __half g_woh[L_*D_*D_],  g_wol[L_*D_*D_];
__device__ __half g_wph[L_*D_*D_],  g_wpl[L_*D_*D_];
__device__ __half g_w1h[L_*D_*FF_], g_w1l[L_*D_*FF_];
__device__ __half g_w2h[L_*FF_*D_], g_w2l[L_*FF_*D_];

// ---------------- PTX helpers (family-portable: sm_80+ ISA only) ----------
__device__ __forceinline__ uint32_t s2u(const void* p) {
    uint32_t a;
    asm("{ .reg .u64 t; cvta.to.shared.u64 t, %1; cvt.u32.u64 %0, t; }" : "=r"(a) : "l"(p));
    return a;
}

#define CPA16(sa, g) \
    asm volatile("cp.async.cg.shared.global [%0], [%1], 16;" :: "r"(sa), "l"(g) : "memory")
#define CPCOMMIT() asm volatile("cp.async.commit_group;" ::: "memory")
#define CPWAIT(n)  asm volatile("cp.async.wait_group %0;" :: "n"(n) : "memory")

#define LDSM4(d0, d1, d2, d3, a) \
    asm volatile("ldmatrix.sync.aligned.m8n8.x4.shared.b16 {%0,%1,%2,%3}, [%4];" \
        : "=r"(d0), "=r"(d1), "=r"(d2), "=r"(d3) : "r"(a))

#define MMA16816(c, a, b0, b1) \
    asm volatile("mma.sync.aligned.m16n8k16.row.col.f32.f16.f16.f32 " \
        "{%0,%1,%2,%3}, {%4,%5,%6,%7}, {%8,%9}, {%0,%1,%2,%3};" \
        : "+f"((c)[0]), "+f"((c)[1]), "+f"((c)[2]), "+f"((c)[3]) \
        : "r"((a)[0]), "r"((a)[1]), "r"((a)[2]), "r"((a)[3]), "r"(b0), "r"(b1))

__device__ __forceinline__ void split_h(float v, __half& hi, __half& lo) {
    hi = __float2half_rn(v);
    lo = __float2half_rn(v - __half2float(hi));
}
__device__ __forceinline__ float dot4(float4 a, float4 b) {
    return a.x * b.x + a.y * b.y + a.z * b.z + a.w * b.w;
}

// ---------------- elementwise scale: x = xs * sqrt(D) ----------------
__global__ void scale_kernel(const float* __restrict__ xs, float s) {
    int i = blockIdx.x * blockDim.x + threadIdx.x;
    g_x[i] = xs[i] * s;
}

// ---------------- pos_emb split: fp32 -> fp16 hi/lo ----------------
__global__ void posconv_kernel(const float* __restrict__ pos) {
    int i = blockIdx.x * blockDim.x + threadIdx.x;
    __half h, l;
    split_h(pos[i], h, l);
    g_posh[i] = h; g_posl[i] = l;
}

// ---------------- bias concat for fused QKV ----------------
__global__ void bcat_kernel(const float* __restrict__ bq, const float* __restrict__ bk,
                            const float* __restrict__ bv) {
    int i = blockIdx.x * blockDim.x + threadIdx.x;   // L*1536
    int l = i / QKVN_, c = i % QKVN_;
    float v = (c < D_) ? bq[l * D_ + c]
            : (c < 2 * D_) ? bk[l * D_ + c - D_]
            : bv[l * D_ + c - 2 * D_];
    g_bqkv[i] = v;
}

// ---------------- weight transpose + split: W[K][N] -> Wt_hi/lo[N][K] ------
// grid (N/32, K/32, L), block (32, 8)
__global__ void wtrans_kernel(const float* __restrict__ W,
                              __half* __restrict__ Th, __half* __restrict__ Tl,
                              int K, int N, size_t srcLS, size_t dstLS) {
    __shared__ float sm[32][33];
    const float* Wl = W + (size_t)blockIdx.z * srcLS;
    __half* Thl = Th + (size_t)blockIdx.z * dstLS;
    __half* Tll = Tl + (size_t)blockIdx.z * dstLS;
    int n0 = blockIdx.x * 32, k0 = blockIdx.y * 32;
    int tx = threadIdx.x, ty = threadIdx.y;
    #pragma unroll
    for (int j = 0; j < 4; j++)
        sm[ty + j * 8][tx] = Wl[(size_t)(k0 + ty + j * 8) * N + n0 + tx];
    __syncthreads();
    #pragma unroll
    for (int j = 0; j < 4; j++) {
        int n = ty + j * 8;
        float v = sm[tx][n];
        __half h, l;
        split_h(v, h, l);
        size_t o = (size_t)(n0 + n) * K + k0 + tx;
        Thl[o] = h; Tll[o] = l;
    }
}

// ---------------- LayerNorm ----------------
__device__ __forceinline__ void ln_stats(const float* x, int tid, float& v0, float& v1,
                                         float& mean, float& inv, float* sh_s, float* sh_ss) {
    v0 = x[tid]; v1 = x[tid + 256];
    float s = v0 + v1, ss = v0 * v0 + v1 * v1;
    int lane = tid & 31, warp = tid >> 5;
    #pragma unroll
    for (int off = 16; off; off >>= 1) {
        s  += __shfl_xor_sync(0xffffffffu, s,  off);
        ss += __shfl_xor_sync(0xffffffffu, ss, off);
    }
    if (lane == 0) { sh_s[warp] = s; sh_ss[warp] = ss; }
    __syncthreads();
    if (warp == 0) {
        float a = (lane < 8) ? sh_s[lane]  : 0.0f;
        float b = (lane < 8) ? sh_ss[lane] : 0.0f;
        #pragma unroll
        for (int off = 4; off; off >>= 1) {
            a += __shfl_xor_sync(0xffffffffu, a, off);
            b += __shfl_xor_sync(0xffffffffu, b, off);
        }
        if (lane == 0) { sh_s[0] = a; sh_ss[0] = b; }
    }
    __syncthreads();
    mean = sh_s[0] * (1.0f / D_);
    float var = sh_ss[0] * (1.0f / D_) - mean * mean;
    inv = rsqrtf(var + 1e-5f);
}

__global__ void ln_kernel(const float* __restrict__ in, float* __restrict__ out,
                          const float* __restrict__ gam, const float* __restrict__ bet) {
    __shared__ float sh_s[8], sh_ss[8];
    int row = blockIdx.x, tid = threadIdx.x;
    const float* x = in + (size_t)row * D_;
    float v0, v1, mean, inv;
    ln_stats(x, tid, v0, v1, mean, inv, sh_s, sh_ss);
    float* y = out + (size_t)row * D_;
    y[tid]       = (v0 - mean) * inv * gam[tid]       + bet[tid];
    y[tid + 256] = (v1 - mean) * inv * gam[tid + 256] + bet[tid + 256];
}

__global__ void ln_h3_kernel(const float* __restrict__ in,
                             __half* __restrict__ oh, __half* __restrict__ ol,
                             const float* __restrict__ gam, const float* __restrict__ bet) {
    __shared__ float sh_s[8], sh_ss[8];
    int row = blockIdx.x, tid = threadIdx.x;
    const float* x = in + (size_t)row * D_;
    float v0, v1, mean, inv;
    ln_stats(x, tid, v0, v1, mean, inv, sh_s, sh_ss);
    float y0 = (v0 - mean) * inv * gam[tid]       + bet[tid];
    float y1 = (v1 - mean) * inv * gam[tid + 256] + bet[tid + 256];
    __half h, l;
    size_t o = (size_t)row * D_ + tid;
    split_h(y0, h, l); oh[o] = h; ol[o] = l;
    split_h(y1, h, l); oh[o + 256] = h; ol[o + 256] = l;
}

// ---------------- HMMA fp16x3 GEMM (3-stage cp.async pipeline) -------------
// C[M x N] = A[M x K] @ W[K x N]; A row-major fp16 hi/lo, W pre-transposed
// as Bt[N][K] fp16 hi/lo. Block 128x128x32, 8 warps, warp tile 64x32.
// One __syncthreads per k-chunk; empty-commit keeps wait invariant at tail.
#define STAGE_BYTES 32768
#define NSTG 3
__global__ void __launch_bounds__(256, 1)
gemm_h3(const __half* __restrict__ Ah, const __half* __restrict__ Al,
        const __half* __restrict__ Bh, const __half* __restrict__ Bl,
        const float* __restrict__ bias, const float* __restrict__ res,
        float* __restrict__ outF,
        __half* __restrict__ outH, __half* __restrict__ outL,
        int N, int K, int relu) {
    extern __shared__ char smem[];
    uint32_t sb = s2u(smem);
    int tid = threadIdx.x, lane = tid & 31, wid = tid >> 5;
    int wm = wid >> 2, wn = wid & 3;
    int rowBase = blockIdx.y * 128, colBase = blockIdx.x * 128;
    int sub = lane & 7, grp = lane >> 3;

    float acc[4][4][4];
    #pragma unroll
    for (int i = 0; i < 4; i++)
        #pragma unroll
        for (int j = 0; j < 4; j++)
            #pragma unroll
            for (int c = 0; c < 4; c++) acc[i][j][c] = 0.0f;

    const int NC = K >> 5;

    auto load_stage = [&](int c, int buf) {
        uint32_t sbase = sb + buf * STAGE_BYTES;
        int k0 = c << 5;
        #pragma unroll
        for (int i = 0; i < 2; i++) {
            int id  = tid + (i << 8);
            int row = id >> 2, ch = id & 3;
            int phys = ch ^ ((row >> 1) & 3);
            uint32_t so = sbase + row * 64 + phys * 16;
            const __half* gA  = Ah + (size_t)(rowBase + row) * K + k0 + ch * 8;
            const __half* gAl = Al + (size_t)(rowBase + row) * K + k0 + ch * 8;
            const __half* gB  = Bh + (size_t)(colBase + row) * K + k0 + ch * 8;
            const __half* gBl = Bl + (size_t)(colBase + row) * K + k0 + ch * 8;
            CPA16(so,          gA);
            CPA16(so + 8192u,  gAl);
            CPA16(so + 16384u, gB);
            CPA16(so + 24576u, gBl);
        }
    };

    auto compute = [&](int buf) {
        uint32_t base = sb + buf * STAGE_BYTES;
        #pragma unroll
        for (int ks = 0; ks < 2; ks++) {
            uint32_t ahf[4][4], alf[4][4], bhf[4][2], blf[4][2];
            #pragma unroll
            for (int mi = 0; mi < 4; mi++) {
                int row = wm * 64 + mi * 16 + sub + (grp & 1) * 8;
                int ci = 2 * ks + (grp >> 1);
                uint32_t ad = base + row * 64 + ((ci ^ ((row >> 1) & 3)) * 16);
                LDSM4(ahf[mi][0], ahf[mi][1], ahf[mi][2], ahf[mi][3], ad);
                LDSM4(alf[mi][0], alf[mi][1], alf[mi][2], alf[mi][3], ad + 8192u);
            }
            #pragma unroll
            for (int g = 0; g < 2; g++) {
                int row = wn * 32 + g * 16 + sub + (grp & 1) * 8;
                int ci = 2 * ks + (grp >> 1);
                uint32_t ad = base + 16384u + row * 64 + ((ci ^ ((row >> 1) & 3)) * 16);
                uint32_t r0, r1, r2, r3;
                LDSM4(r0, r1, r2, r3, ad);
                bhf[2*g][0] = r0; bhf[2*g+1][0] = r1; bhf[2*g][1] = r2; bhf[2*g+1][1] = r3;
                LDSM4(r0, r1, r2, r3, ad + 8192u);
                blf[2*g][0] = r0; blf[2*g+1][0] = r1; blf[2*g][1] = r2; blf[2*g+1][1] = r3;
            }
            #pragma unroll
            for (int mi = 0; mi < 4; mi++)
                #pragma unroll
                for (int nj = 0; nj < 4; nj++)
                    MMA16816(acc[mi][nj], ahf[mi], bhf[nj][0], bhf[nj][1]);
            #pragma unroll
            for (int mi = 0; mi < 4; mi++)
                #pragma unroll
                for (int nj = 0; nj < 4; nj++)
                    MMA16816(acc[mi][nj], ahf[mi], blf[nj][0], blf[nj][1]);
            #pragma unroll
            for (int mi = 0; mi < 4; mi++)
                #pragma unroll
                for (int nj = 0; nj < 4; nj++)
                    MMA16816(acc[mi][nj], alf[mi], bhf[nj][0], bhf[nj][1]);
        }
    };

    // prologue: stages 0..NSTG-2, one commit-group each
    #pragma unroll
    for (int s = 0; s < NSTG - 1; s++) {
        load_stage(s, s);
        CPCOMMIT();
    }
    #pragma unroll 1
    for (int c = 0; c < NC; c++) {
        CPWAIT(NSTG - 2);            // stage c complete
        __syncthreads();             // cross-thread visibility + reuse hazard
        if (c + NSTG - 1 < NC) load_stage(c + NSTG - 1, (c + NSTG - 1) % NSTG);
        CPCOMMIT();                  // commit (possibly empty) keeps invariant
        compute(c % NSTG);
    }

    // --- epilogue ---
    #pragma unroll
    for (int mi = 0; mi < 4; mi++) {
        #pragma unroll
        for (int nj = 0; nj < 4; nj++) {
            int r = rowBase + wm * 64 + mi * 16 + (lane >> 2);
            int c = colBase + wn * 32 + nj * 8 + ((lane & 3) << 1);
            #pragma unroll
            for (int half_ : {0, 1}) {
                int rr = r + half_ * 8;
                float v0 = acc[mi][nj][half_ * 2 + 0];
                float v1 = acc[mi][nj][half_ * 2 + 1];
                if (bias) { v0 += bias[c]; v1 += bias[c + 1]; }
                if (res) {
                    float2 rv = *(const float2*)(res + (size_t)rr * N + c);
                    v0 += rv.x; v1 += rv.y;
                }
                if (relu) { v0 = fmaxf(v0, 0.0f); v1 = fmaxf(v1, 0.0f); }
                if (outF)
                    *(float2*)(outF + (size_t)rr * N + c) = make_float2(v0, v1);
                if (outH) {
                    __half h0, l0, h1, l1;
                    split_h(v0, h0, l0);
                    split_h(v1, h1, l1);
                    *(__half2*)(outH + (size_t)rr * N + c) = __halves2half2(h0, h1);
                    *(__half2*)(outL + (size_t)rr * N + c) = __halves2half2(l0, l1);
                }
            }
        }
    }
}

// ---------------- Chunked local attention (reads fused QKV + p_all) --------
__global__ void attn_kernel(const float* __restrict__ qkv, const float* __restrict__ p,
                            const float* __restrict__ pbu, const float* __restrict__ pbv,
                            __half* __restrict__ oh, __half* __restrict__ ol) {
    int ci = blockIdx.x, h = blockIdx.y, b = blockIdx.z;
    int s0 = max((ci - LC_) * CS_, 0);
    int s1 = (ci + 1) * CS_;
    int W = s1 - s0;
    int t0 = ci * CS_;
    int tid = threadIdx.x;                    // 256 threads

    extern __shared__ float sm[];
    float* Ks = sm;
    float* Ps = Ks + WMAX_ * 64;
    float* Vs = Ps + WMAX_ * 64;
    float* QU = Vs + WMAX_ * 64;
    float* QV = QU + 16 * 64;
    float* SC = QV + 16 * 64;

    for (int idx = tid; idx < W * 64; idx += 256) {
        int s = idx >> 6, d = idx & 63;
        size_t gi = (size_t)((b * T_) + s0 + s) * QKVN_ + h * DK_ + d;
        Ks[idx] = qkv[gi + D_];
        Vs[idx] = qkv[gi + 2 * D_];
        Ps[idx] = p[(size_t)(s0 + s) * PALLN_ + h * DK_ + d];
    }
    for (int idx = tid; idx < 16 * 64; idx += 256) {
        int qi = idx >> 6, d = idx & 63;
        float qv_ = qkv[(size_t)((b * T_) + t0 + qi) * QKVN_ + h * DK_ + d];
        QU[idx] = qv_ + pbu[h * DK_ + d];
        QV[idx] = qv_ + pbv[h * DK_ + d];
    }
    __syncthreads();

    const float scale = 0.125f;
    // scores: 2x2 register blocking, float4 smem loads
    int Wh = W >> 1;
    for (int it = tid; it < 8 * Wh; it += 256) {
        int qi = (it / Wh) * 2, s = (it % Wh) * 2;
        float a00 = 0, a01 = 0, a10 = 0, a11 = 0;
        #pragma unroll 4
        for (int d = 0; d < 64; d += 4) {
            float4 qu0 = *(const float4*)&QU[qi * 64 + d];
            float4 qu1 = *(const float4*)&QU[(qi + 1) * 64 + d];
            float4 qv0 = *(const float4*)&QV[qi * 64 + d];
            float4 qv1 = *(const float4*)&QV[(qi + 1) * 64 + d];
            float4 k0 = *(const float4*)&Ks[s * 64 + d];
            float4 k1 = *(const float4*)&Ks[(s + 1) * 64 + d];
            float4 p0 = *(const float4*)&Ps[s * 64 + d];
            float4 p1 = *(const float4*)&Ps[(s + 1) * 64 + d];
            a00 += dot4(qu0, k0) + dot4(qv0, p0);
            a01 += dot4(qu0, k1) + dot4(qv0, p1);
            a10 += dot4(qu1, k0) + dot4(qv1, p0);
            a11 += dot4(qu1, k1) + dot4(qv1, p1);
        }
        SC[qi * WMAX_ + s]           = a00 * scale;
        SC[qi * WMAX_ + s + 1]       = a01 * scale;
        SC[(qi + 1) * WMAX_ + s]     = a10 * scale;
        SC[(qi + 1) * WMAX_ + s + 1] = a11 * scale;
    }
    __syncthreads();

    int warp = tid >> 5, lane = tid & 31;
    for (int qi = warp; qi < 16; qi += 8) {
        float m = -1e30f;
        for (int s = lane; s < W; s += 32) m = fmaxf(m, SC[qi * WMAX_ + s]);
        #pragma unroll
        for (int off = 16; off; off >>= 1) m = fmaxf(m, __shfl_xor_sync(0xffffffffu, m, off));
        float sum = 0.0f;
        for (int s = lane; s < W; s += 32) {
            float e = expf(SC[qi * WMAX_ + s] - m);
            SC[qi * WMAX_ + s] = e;
            sum += e;
        }
        #pragma unroll
        for (int off = 16; off; off >>= 1) sum += __shfl_xor_sync(0xffffffffu, sum, off);
        float inv = 1.0f / sum;
        for (int s = lane; s < W; s += 32) SC[qi * WMAX_ + s] *= inv;
    }
    __syncthreads();

    // A @ V: 2-qi x 2-d blocking, float2 loads; 256 items exactly
    {
        int it = tid;                       // 8 * 32 = 256
        int qi = (it >> 5) * 2, d = (it & 31) * 2;
        float a00 = 0, a01 = 0, a10 = 0, a11 = 0;
        for (int s = 0; s < W; s++) {
            float2 vv = *(const float2*)&Vs[s * 64 + d];
            float c0 = SC[qi * WMAX_ + s];
            float c1 = SC[(qi + 1) * WMAX_ + s];
            a00 += c0 * vv.x; a01 += c0 * vv.y;
            a10 += c1 * vv.x; a11 += c1 * vv.y;
        }
        __half h0, l0, h1, l1;
        size_t o0 = (size_t)((b * T_) + t0 + qi) * D_ + h * DK_ + d;
        size_t o1 = o0 + D_;
        split_h(a00, h0, l0); split_h(a01, h1, l1);
        *(__half2*)(oh + o0) = __halves2half2(h0, h1);
        *(__half2*)(ol + o0) = __halves2half2(l0, l1);
        split_h(a10, h0, l0); split_h(a11, h1, l1);
        *(__half2*)(oh + o1) = __halves2half2(h0, h1);
        *(__half2*)(ol + o1) = __halves2half2(l0, l1);
    }
}

static const int ATTN_SMEM = (WMAX_ * 64 * 3 + 16 * 64 * 2 + 16 * WMAX_) * (int)sizeof(float);
static const int GEMM_SMEM = NSTG * STAGE_BYTES;   // 98304

extern "C" void kernel_launch(void* const* d_in, const int* in_sizes, int n_in,
                              void* d_out, int out_size) {
    (void)in_sizes; (void)n_in; (void)out_size;
    const float* xs    = (const float*)d_in[0];
    const float* pos   = (const float*)d_in[1];
    // d_in[2] = mask: unused (window computed analytically)
    const float* Wq    = (const float*)d_in[3];
    const float* bq    = (const float*)d_in[4];
    const float* Wk    = (const float*)d_in[5];
    const float* bk    = (const float*)d_in[6];
    const float* Wv    = (const float*)d_in[7];
    const float* bv    = (const float*)d_in[8];
    const float* Wo    = (const float*)d_in[9];
    const float* bo    = (const float*)d_in[10];
    const float* Wp    = (const float*)d_in[11];
    const float* pbu   = (const float*)d_in[12];
    const float* pbv   = (const float*)d_in[13];
    const float* ln1s  = (const float*)d_in[14];
    const float* ln1b  = (const float*)d_in[15];
    const float* ln2s  = (const float*)d_in[16];
    const float* ln2b  = (const float*)d_in[17];
    const float* W1    = (const float*)d_in[18];
    const float* b1    = (const float*)d_in[19];
    const float* W2    = (const float*)d_in[20];
    const float* b2    = (const float*)d_in[21];
    const float* lnfs  = (const float*)d_in[22];
    const float* lnfb  = (const float*)d_in[23];

    cudaFuncSetAttribute(attn_kernel, cudaFuncAttributeMaxDynamicSharedMemorySize, ATTN_SMEM);
    cudaFuncSetAttribute(gemm_h3,     cudaFuncAttributeMaxDynamicSharedMemorySize, GEMM_SMEM);

    void* a;
    #define SYM(p, s) cudaGetSymbolAddress(&a, s); auto* p = (decltype(&s[0]))a;
    SYM(px, g_x)  SYM(pqkv, g_qkv)  SYM(ppall, g_pall)  SYM(pbqkv, g_bqkv)
    SYM(phh, g_hh) SYM(phl, g_hl)
    SYM(poh, g_oh) SYM(pol, g_ol)
    SYM(pffh, g_ffh) SYM(pffl, g_ffl)
    SYM(pposh, g_posh) SYM(pposl, g_posl)
    SYM(pwqkvh, g_wqkvh) SYM(pwqkvl, g_wqkvl)
    SYM(pwoh, g_woh) SYM(pwol, g_wol)
    SYM(pwph, g_wph) SYM(pwpl, g_wpl)
    SYM(pw1h, g_w1h) SYM(pw1l, g_w1l)
    SYM(pw2h, g_w2h) SYM(pw2l, g_w2l)
    #undef SYM

    const int M = B_ * T_;  // 4096
    const size_t DD = (size_t)D_ * D_;          // 262144
    const size_t QKVLS = (size_t)QKVN_ * D_;    // 786432

    // prep: x scale, pos split, bias concat, weight transpose+split
    scale_kernel<<<(B_*T_*D_) / 256, 256>>>(xs, sqrtf((float)D_));
    posconv_kernel<<<(T_*D_) / 256, 256>>>(pos);
    bcat_kernel<<<(L_*QKVN_) / 256, 256>>>(bq, bk, bv);
    dim3 wtb(32, 8);
    wtrans_kernel<<<dim3(D_/32,  D_/32,  L_), wtb>>>(Wq, pwqkvh,          pwqkvl,          D_, D_, DD, QKVLS);
    wtrans_kernel<<<dim3(D_/32,  D_/32,  L_), wtb>>>(Wk, pwqkvh + DD,     pwqkvl + DD,     D_, D_, DD, QKVLS);
    wtrans_kernel<<<dim3(D_/32,  D_/32,  L_), wtb>>>(Wv, pwqkvh + 2*DD,   pwqkvl + 2*DD,   D_, D_, DD, QKVLS);
    wtrans_kernel<<<dim3(D_/32,  D_/32,  L_), wtb>>>(Wo, pwoh, pwol, D_,  D_,  DD, DD);
    wtrans_kernel<<<dim3(D_/32,  D_/32,  L_), wtb>>>(Wp, pwph, pwpl, D_,  D_,  DD, DD);
    wtrans_kernel<<<dim3(FF_/32, D_/32,  L_), wtb>>>(W1, pw1h, pw1l, D_,  FF_, (size_t)D_*FF_, (size_t)D_*FF_);
    wtrans_kernel<<<dim3(D_/32,  FF_/32, L_), wtb>>>(W2, pw2h, pw2l, FF_, D_,  (size_t)FF_*D_, (size_t)FF_*D_);

    // p_all = pos_emb @ Wp (all 6 layers in one GEMM, N = L*D = 3072)
    gemm_h3<<<dim3(PALLN_/128, T_/128), 256, GEMM_SMEM>>>(pposh, pposl, pwph, pwpl,
        nullptr, nullptr, ppall, nullptr, nullptr, PALLN_, D_, 0);

    for (int l = 0; l < L_; l++) {
        size_t wdf = (size_t)l * D_ * FF_;

        // h = LN1(x)  (fp16 hi/lo)
        ln_h3_kernel<<<M, 256>>>(px, phh, phl, ln1s + l * D_, ln1b + l * D_);

        // qkv = h @ [Wq|Wk|Wv] + [bq|bk|bv]   (fused, fp32 out)
        gemm_h3<<<dim3(QKVN_/128, M/128), 256, GEMM_SMEM>>>(phh, phl,
            pwqkvh + l * QKVLS, pwqkvl + l * QKVLS,
            pbqkv + l * QKVN_, nullptr, pqkv, nullptr, nullptr, QKVN_, D_, 0);

        // attention (chunked local) -> o hi/lo
        attn_kernel<<<dim3(NCHUNK_, H_, B_), 256, ATTN_SMEM>>>(
            pqkv, ppall + l * D_, pbu + l * H_ * DK_, pbv + l * H_ * DK_, poh, pol);

        // x = x + o @ Wo + bo
        gemm_h3<<<dim3(D_/128, M/128), 256, GEMM_SMEM>>>(poh, pol,
            pwoh + l * DD, pwol + l * DD,
            bo + l*D_, px, px, nullptr, nullptr, D_, D_, 0);

        // h2 = LN2(x)  (fp16 hi/lo)
        ln_h3_kernel<<<M, 256>>>(px, phh, phl, ln2s + l * D_, ln2b + l * D_);

        // ff = relu(h2 @ W1 + b1)  (fp16 hi/lo out only)
        gemm_h3<<<dim3(FF_/128, M/128), 256, GEMM_SMEM>>>(phh, phl,
            pw1h + wdf, pw1l + wdf,
            b1 + l*FF_, nullptr, nullptr, pffh, pffl, FF_, D_, 1);

        // x = x + ff @ W2 + b2
        gemm_h3<<<dim3(D_/128, M/128), 256, GEMM_SMEM>>>(pffh, pffl,
            pw2h + wdf, pw2l + wdf,
            b2 + l*D_, px, px, nullptr, nullptr, D_, FF_, 0);
    }

    // out = LNf(x)  (fp32)
    ln_kernel<<<M, 256>>>(px, (float*)d_out, lnfs, lnfb);
}

// round 5
// speedup vs baseline: 2.4517x; 1.0285x over previous
#include <cuda_runtime.h>
#include <cuda_fp16.h>
#include <math.h>
#include <stdint.h>

// Problem constants
#define B_  8
#define T_  512
#define D_  512
#define H_  8
#define FF_ 2048
#define L_  6
#define CS_ 16
#define LC_ 4
#define DK_ 64
#define NCHUNK_ (T_ / CS_)          // 32
#define WMAX_ ((LC_ + 1) * CS_)     // 80
#define QKVN_ (3 * D_)              // 1536
#define PALLN_ (L_ * D_)            // 3072

// ---------------- scratch (device globals; no allocation) ----------------
__device__ float g_x   [B_*T_*D_];
__device__ float g_qkv [B_*T_*QKVN_];
__device__ float g_pall[T_*PALLN_];
__device__ float g_bqkv[L_*QKVN_];

__device__ __half g_hh [B_*T_*D_],  g_hl [B_*T_*D_];   // LN output hi/lo
__device__ __half g_oh [B_*T_*D_],  g_ol [B_*T_*D_];   // attention out hi/lo
__device__ __half g_ffh[B_*T_*FF_], g_ffl[B_*T_*FF_];  // FF1 out hi/lo
__device__ __half g_posh[T_*D_],    g_posl[T_*D_];     // pos_emb hi/lo

// transposed + split weights: Wt[n][k]
__device__ __half g_wqkvh[L_*QKVN_*D_], g_wqkvl[L_*QKVN_*D_];
__device__ __half g_woh[L_*D_*D_],  g_wol[L_*D_*D_];
__device__ __half g_wph[L_*D_*D_],  g_wpl[L_*D_*D_];
__device__ __half g_w1h[L_*D_*FF_], g_w1l[L_*D_*FF_];
__device__ __half g_w2h[L_*FF_*D_], g_w2l[L_*FF_*D_];

// ---------------- PTX helpers (family-portable: sm_80+ ISA only) ----------
__device__ __forceinline__ uint32_t s2u(const void* p) {
    uint32_t a;
    asm("{ .reg .u64 t; cvta.to.shared.u64 t, %1; cvt.u32.u64 %0, t; }" : "=r"(a) : "l"(p));
    return a;
}

#define CPA16(sa, g) \
    asm volatile("cp.async.cg.shared.global [%0], [%1], 16;" :: "r"(sa), "l"(g) : "memory")
#define CPCOMMIT() asm volatile("cp.async.commit_group;" ::: "memory")
#define CPWAIT(n)  asm volatile("cp.async.wait_group %0;" :: "n"(n) : "memory")

#define LDSM4(d0, d1, d2, d3, a) \
    asm volatile("ldmatrix.sync.aligned.m8n8.x4.shared.b16 {%0,%1,%2,%3}, [%4];" \
        : "=r"(d0), "=r"(d1), "=r"(d2), "=r"(d3) : "r"(a))

#define MMA16816(c, a, b0, b1) \
    asm volatile("mma.sync.aligned.m16n8k16.row.col.f32.f16.f16.f32 " \
        "{%0,%1,%2,%3}, {%4,%5,%6,%7}, {%8,%9}, {%0,%1,%2,%3};" \
        : "+f"((c)[0]), "+f"((c)[1]), "+f"((c)[2]), "+f"((c)[3]) \
        : "r"((a)[0]), "r"((a)[1]), "r"((a)[2]), "r"((a)[3]), "r"(b0), "r"(b1))

__device__ __forceinline__ void split_h(float v, __half& hi, __half& lo) {
    hi = __float2half_rn(v);
    lo = __float2half_rn(v - __half2float(hi));
}
__device__ __forceinline__ float dot4(float4 a, float4 b) {
    return a.x * b.x + a.y * b.y + a.z * b.z + a.w * b.w;
}

// ---------------- elementwise scale: x = xs * sqrt(D) ----------------
__global__ void scale_kernel(const float* __restrict__ xs, float s) {
    int i = blockIdx.x * blockDim.x + threadIdx.x;
    g_x[i] = xs[i] * s;
}

// ---------------- pos_emb split: fp32 -> fp16 hi/lo ----------------
__global__ void posconv_kernel(const float* __restrict__ pos) {
    int i = blockIdx.x * blockDim.x + threadIdx.x;
    __half h, l;
    split_h(pos[i], h, l);
    g_posh[i] = h; g_posl[i] = l;
}

// ---------------- bias concat for fused QKV ----------------
__global__ void bcat_kernel(const float* __restrict__ bq, const float* __restrict__ bk,
                            const float* __restrict__ bv) {
    int i = blockIdx.x * blockDim.x + threadIdx.x;   // L*1536
    int l = i / QKVN_, c = i % QKVN_;
    float v = (c < D_) ? bq[l * D_ + c]
            : (c < 2 * D_) ? bk[l * D_ + c - D_]
            : bv[l * D_ + c - 2 * D_];
    g_bqkv[i] = v;
}

// ---------------- weight transpose + split: W[K][N] -> Wt_hi/lo[N][K] ------
// grid (N/32, K/32, L), block (32, 8)
__global__ void wtrans_kernel(const float* __restrict__ W,
                              __half* __restrict__ Th, __half* __restrict__ Tl,
                              int K, int N, size_t srcLS, size_t dstLS) {
    __shared__ float sm[32][33];
    const float* Wl = W + (size_t)blockIdx.z * srcLS;
    __half* Thl = Th + (size_t)blockIdx.z * dstLS;
    __half* Tll = Tl + (size_t)blockIdx.z * dstLS;
    int n0 = blockIdx.x * 32, k0 = blockIdx.y * 32;
    int tx = threadIdx.x, ty = threadIdx.y;
    #pragma unroll
    for (int j = 0; j < 4; j++)
        sm[ty + j * 8][tx] = Wl[(size_t)(k0 + ty + j * 8) * N + n0 + tx];
    __syncthreads();
    #pragma unroll
    for (int j = 0; j < 4; j++) {
        int n = ty + j * 8;
        float v = sm[tx][n];
        __half h, l;
        split_h(v, h, l);
        size_t o = (size_t)(n0 + n) * K + k0 + tx;
        Thl[o] = h; Tll[o] = l;
    }
}

// ---------------- LayerNorm ----------------
__device__ __forceinline__ void ln_stats(const float* x, int tid, float& v0, float& v1,
                                         float& mean, float& inv, float* sh_s, float* sh_ss) {
    v0 = x[tid]; v1 = x[tid + 256];
    float s = v0 + v1, ss = v0 * v0 + v1 * v1;
    int lane = tid & 31, warp = tid >> 5;
    #pragma unroll
    for (int off = 16; off; off >>= 1) {
        s  += __shfl_xor_sync(0xffffffffu, s,  off);
        ss += __shfl_xor_sync(0xffffffffu, ss, off);
    }
    if (lane == 0) { sh_s[warp] = s; sh_ss[warp] = ss; }
    __syncthreads();
    if (warp == 0) {
        float a = (lane < 8) ? sh_s[lane]  : 0.0f;
        float b = (lane < 8) ? sh_ss[lane] : 0.0f;
        #pragma unroll
        for (int off = 4; off; off >>= 1) {
            a += __shfl_xor_sync(0xffffffffu, a, off);
            b += __shfl_xor_sync(0xffffffffu, b, off);
        }
        if (lane == 0) { sh_s[0] = a; sh_ss[0] = b; }
    }
    __syncthreads();
    mean = sh_s[0] * (1.0f / D_);
    float var = sh_ss[0] * (1.0f / D_) - mean * mean;
    inv = rsqrtf(var + 1e-5f);
}

__global__ void ln_kernel(const float* __restrict__ in, float* __restrict__ out,
                          const float* __restrict__ gam, const float* __restrict__ bet) {
    __shared__ float sh_s[8], sh_ss[8];
    int row = blockIdx.x, tid = threadIdx.x;
    const float* x = in + (size_t)row * D_;
    float v0, v1, mean, inv;
    ln_stats(x, tid, v0, v1, mean, inv, sh_s, sh_ss);
    float* y = out + (size_t)row * D_;
    y[tid]       = (v0 - mean) * inv * gam[tid]       + bet[tid];
    y[tid + 256] = (v1 - mean) * inv * gam[tid + 256] + bet[tid + 256];
}

__global__ void ln_h3_kernel(const float* __restrict__ in,
                             __half* __restrict__ oh, __half* __restrict__ ol,
                             const float* __restrict__ gam, const float* __restrict__ bet) {
    __shared__ float sh_s[8], sh_ss[8];
    int row = blockIdx.x, tid = threadIdx.x;
    const float* x = in + (size_t)row * D_;
    float v0, v1, mean, inv;
    ln_stats(x, tid, v0, v1, mean, inv, sh_s, sh_ss);
    float y0 = (v0 - mean) * inv * gam[tid]       + bet[tid];
    float y1 = (v1 - mean) * inv * gam[tid + 256] + bet[tid + 256];
    __half h, l;
    size_t o = (size_t)row * D_ + tid;
    split_h(y0, h, l); oh[o] = h; ol[o] = l;
    split_h(y1, h, l); oh[o + 256] = h; ol[o + 256] = l;
}

// ---------------- HMMA fp16x3 GEMM (2-stage cp.async, 2 CTAs/SM) -----------
// C[M x N] = A[M x K] @ W[K x N]; A row-major fp16 hi/lo, W pre-transposed
// as Bt[N][K] fp16 hi/lo. Block 128x128x32, 8 warps, warp tile 64x32.
// 64KB smem (2 stages) -> 2 resident CTAs/SM fill sync/epilogue bubbles.
#define STAGE_BYTES 32768
#define NSTG 2
__global__ void __launch_bounds__(256, 2)
gemm_h3(const __half* __restrict__ Ah, const __half* __restrict__ Al,
        const __half* __restrict__ Bh, const __half* __restrict__ Bl,
        const float* __restrict__ bias, const float* __restrict__ res,
        float* __restrict__ outF,
        __half* __restrict__ outH, __half* __restrict__ outL,
        int N, int K, int relu) {
    extern __shared__ char smem[];
    uint32_t sb = s2u(smem);
    int tid = threadIdx.x, lane = tid & 31, wid = tid >> 5;
    int wm = wid >> 2, wn = wid & 3;
    int rowBase = blockIdx.y * 128, colBase = blockIdx.x * 128;
    int sub = lane & 7, grp = lane >> 3;

    float acc[4][4][4];
    #pragma unroll
    for (int i = 0; i < 4; i++)
        #pragma unroll
        for (int j = 0; j < 4; j++)
            #pragma unroll
            for (int c = 0; c < 4; c++) acc[i][j][c] = 0.0f;

    const int NC = K >> 5;

    auto load_stage = [&](int c, int buf) {
        uint32_t sbase = sb + buf * STAGE_BYTES;
        int k0 = c << 5;
        #pragma unroll
        for (int i = 0; i < 2; i++) {
            int id  = tid + (i << 8);
            int row = id >> 2, ch = id & 3;
            int phys = ch ^ ((row >> 1) & 3);
            uint32_t so = sbase + row * 64 + phys * 16;
            const __half* gA  = Ah + (size_t)(rowBase + row) * K + k0 + ch * 8;
            const __half* gAl = Al + (size_t)(rowBase + row) * K + k0 + ch * 8;
            const __half* gB  = Bh + (size_t)(colBase + row) * K + k0 + ch * 8;
            const __half* gBl = Bl + (size_t)(colBase + row) * K + k0 + ch * 8;
            CPA16(so,          gA);
            CPA16(so + 8192u,  gAl);
            CPA16(so + 16384u, gB);
            CPA16(so + 24576u, gBl);
        }
    };

    auto compute = [&](int buf) {
        uint32_t base = sb + buf * STAGE_BYTES;
        #pragma unroll
        for (int ks = 0; ks < 2; ks++) {
            uint32_t ahf[4][4], alf[4][4], bhf[4][2], blf[4][2];
            #pragma unroll
            for (int mi = 0; mi < 4; mi++) {
                int row = wm * 64 + mi * 16 + sub + (grp & 1) * 8;
                int ci = 2 * ks + (grp >> 1);
                uint32_t ad = base + row * 64 + ((ci ^ ((row >> 1) & 3)) * 16);
                LDSM4(ahf[mi][0], ahf[mi][1], ahf[mi][2], ahf[mi][3], ad);
                LDSM4(alf[mi][0], alf[mi][1], alf[mi][2], alf[mi][3], ad + 8192u);
            }
            #pragma unroll
            for (int g = 0; g < 2; g++) {
                int row = wn * 32 + g * 16 + sub + (grp & 1) * 8;
                int ci = 2 * ks + (grp >> 1);
                uint32_t ad = base + 16384u + row * 64 + ((ci ^ ((row >> 1) & 3)) * 16);
                uint32_t r0, r1, r2, r3;
                LDSM4(r0, r1, r2, r3, ad);
                bhf[2*g][0] = r0; bhf[2*g+1][0] = r1; bhf[2*g][1] = r2; bhf[2*g+1][1] = r3;
                LDSM4(r0, r1, r2, r3, ad + 8192u);
                blf[2*g][0] = r0; blf[2*g+1][0] = r1; blf[2*g][1] = r2; blf[2*g+1][1] = r3;
            }
            #pragma unroll
            for (int mi = 0; mi < 4; mi++)
                #pragma unroll
                for (int nj = 0; nj < 4; nj++)
                    MMA16816(acc[mi][nj], ahf[mi], bhf[nj][0], bhf[nj][1]);
            #pragma unroll
            for (int mi = 0; mi < 4; mi++)
                #pragma unroll
                for (int nj = 0; nj < 4; nj++)
                    MMA16816(acc[mi][nj], ahf[mi], blf[nj][0], blf[nj][1]);
            #pragma unroll
            for (int mi = 0; mi < 4; mi++)
                #pragma unroll
                for (int nj = 0; nj < 4; nj++)
                    MMA16816(acc[mi][nj], alf[mi], bhf[nj][0], bhf[nj][1]);
        }
    };

    // prologue: stage 0
    load_stage(0, 0);
    CPCOMMIT();
    #pragma unroll 1
    for (int c = 0; c < NC; c++) {
        CPWAIT(0);                   // stage c complete
        __syncthreads();             // cross-thread visibility + reuse hazard
        if (c + 1 < NC) load_stage(c + 1, (c + 1) & 1);
        CPCOMMIT();                  // commit (possibly empty) keeps pattern
        compute(c & 1);
    }

    // --- epilogue ---
    #pragma unroll
    for (int mi = 0; mi < 4; mi++) {
        #pragma unroll
        for (int nj = 0; nj < 4; nj++) {
            int r = rowBase + wm * 64 + mi * 16 + (lane >> 2);
            int c = colBase + wn * 32 + nj * 8 + ((lane & 3) << 1);
            #pragma unroll
            for (int half_ : {0, 1}) {
                int rr = r + half_ * 8;
                float v0 = acc[mi][nj][half_ * 2 + 0];
                float v1 = acc[mi][nj][half_ * 2 + 1];
                if (bias) { v0 += bias[c]; v1 += bias[c + 1]; }
                if (res) {
                    float2 rv = *(const float2*)(res + (size_t)rr * N + c);
                    v0 += rv.x; v1 += rv.y;
                }
                if (relu) { v0 = fmaxf(v0, 0.0f); v1 = fmaxf(v1, 0.0f); }
                if (outF)
                    *(float2*)(outF + (size_t)rr * N + c) = make_float2(v0, v1);
                if (outH) {
                    __half h0, l0, h1, l1;
                    split_h(v0, h0, l0);
                    split_h(v1, h1, l1);
                    *(__half2*)(outH + (size_t)rr * N + c) = __halves2half2(h0, h1);
                    *(__half2*)(outL + (size_t)rr * N + c) = __halves2half2(l0, l1);
                }
            }
        }
    }
}

// ---------------- Chunked local attention (reads fused QKV + p_all) --------
__global__ void attn_kernel(const float* __restrict__ qkv, const float* __restrict__ p,
                            const float* __restrict__ pbu, const float* __restrict__ pbv,
                            __half* __restrict__ oh, __half* __restrict__ ol) {
    int ci = blockIdx.x, h = blockIdx.y, b = blockIdx.z;
    int s0 = max((ci - LC_) * CS_, 0);
    int s1 = (ci + 1) * CS_;
    int W = s1 - s0;
    int t0 = ci * CS_;
    int tid = threadIdx.x;                    // 256 threads

    extern __shared__ float sm[];
    float* Ks = sm;
    float* Ps = Ks + WMAX_ * 64;
    float* Vs = Ps + WMAX_ * 64;
    float* QU = Vs + WMAX_ * 64;
    float* QV = QU + 16 * 64;
    float* SC = QV + 16 * 64;

    for (int idx = tid; idx < W * 64; idx += 256) {
        int s = idx >> 6, d = idx & 63;
        size_t gi = (size_t)((b * T_) + s0 + s) * QKVN_ + h * DK_ + d;
        Ks[idx] = qkv[gi + D_];
        Vs[idx] = qkv[gi + 2 * D_];
        Ps[idx] = p[(size_t)(s0 + s) * PALLN_ + h * DK_ + d];
    }
    for (int idx = tid; idx < 16 * 64; idx += 256) {
        int qi = idx >> 6, d = idx & 63;
        float qv_ = qkv[(size_t)((b * T_) + t0 + qi) * QKVN_ + h * DK_ + d];
        QU[idx] = qv_ + pbu[h * DK_ + d];
        QV[idx] = qv_ + pbv[h * DK_ + d];
    }
    __syncthreads();

    const float scale = 0.125f;
    // scores: 2x2 register blocking, float4 smem loads
    int Wh = W >> 1;
    for (int it = tid; it < 8 * Wh; it += 256) {
        int qi = (it / Wh) * 2, s = (it % Wh) * 2;
        float a00 = 0, a01 = 0, a10 = 0, a11 = 0;
        #pragma unroll 4
        for (int d = 0; d < 64; d += 4) {
            float4 qu0 = *(const float4*)&QU[qi * 64 + d];
            float4 qu1 = *(const float4*)&QU[(qi + 1) * 64 + d];
            float4 qv0 = *(const float4*)&QV[qi * 64 + d];
            float4 qv1 = *(const float4*)&QV[(qi + 1) * 64 + d];
            float4 k0 = *(const float4*)&Ks[s * 64 + d];
            float4 k1 = *(const float4*)&Ks[(s + 1) * 64 + d];
            float4 p0 = *(const float4*)&Ps[s * 64 + d];
            float4 p1 = *(const float4*)&Ps[(s + 1) * 64 + d];
            a00 += dot4(qu0, k0) + dot4(qv0, p0);
            a01 += dot4(qu0, k1) + dot4(qv0, p1);
            a10 += dot4(qu1, k0) + dot4(qv1, p0);
            a11 += dot4(qu1, k1) + dot4(qv1, p1);
        }
        SC[qi * WMAX_ + s]           = a00 * scale;
        SC[qi * WMAX_ + s + 1]       = a01 * scale;
        SC[(qi + 1) * WMAX_ + s]     = a10 * scale;
        SC[(qi + 1) * WMAX_ + s + 1] = a11 * scale;
    }
    __syncthreads();

    int warp = tid >> 5, lane = tid & 31;
    for (int qi = warp; qi < 16; qi += 8) {
        float m = -1e30f;
        for (int s = lane; s < W; s += 32) m = fmaxf(m, SC[qi * WMAX_ + s]);
        #pragma unroll
        for (int off = 16; off; off >>= 1) m = fmaxf(m, __shfl_xor_sync(0xffffffffu, m, off));
        float sum = 0.0f;
        for (int s = lane; s < W; s += 32) {
            float e = expf(SC[qi * WMAX_ + s] - m);
            SC[qi * WMAX_ + s] = e;
            sum += e;
        }
        #pragma unroll
        for (int off = 16; off; off >>= 1) sum += __shfl_xor_sync(0xffffffffu, sum, off);
        float inv = 1.0f / sum;
        for (int s = lane; s < W; s += 32) SC[qi * WMAX_ + s] *= inv;
    }
    __syncthreads();

    // A @ V: 2-qi x 2-d blocking, float2 loads; 256 items exactly
    {
        int it = tid;                       // 8 * 32 = 256
        int qi = (it >> 5) * 2, d = (it & 31) * 2;
        float a00 = 0, a01 = 0, a10 = 0, a11 = 0;
        for (int s = 0; s < W; s++) {
            float2 vv = *(const float2*)&Vs[s * 64 + d];
            float c0 = SC[qi * WMAX_ + s];
            float c1 = SC[(qi + 1) * WMAX_ + s];
            a00 += c0 * vv.x; a01 += c0 * vv.y;
            a10 += c1 * vv.x; a11 += c1 * vv.y;
        }
        __half h0, l0, h1, l1;
        size_t o0 = (size_t)((b * T_) + t0 + qi) * D_ + h * DK_ + d;
        size_t o1 = o0 + D_;
        split_h(a00, h0, l0); split_h(a01, h1, l1);
        *(__half2*)(oh + o0) = __halves2half2(h0, h1);
        *(__half2*)(ol + o0) = __halves2half2(l0, l1);
        split_h(a10, h0, l0); split_h(a11, h1, l1);
        *(__half2*)(oh + o1) = __halves2half2(h0, h1);
        *(__half2*)(ol + o1) = __halves2half2(l0, l1);
    }
}

static const int ATTN_SMEM = (WMAX_ * 64 * 3 + 16 * 64 * 2 + 16 * WMAX_) * (int)sizeof(float);
static const int GEMM_SMEM = NSTG * STAGE_BYTES;   // 65536

extern "C" void kernel_launch(void* const* d_in, const int* in_sizes, int n_in,
                              void* d_out, int out_size) {
    (void)in_sizes; (void)n_in; (void)out_size;
    const float* xs    = (const float*)d_in[0];
    const float* pos   = (const float*)d_in[1];
    // d_in[2] = mask: unused (window computed analytically)
    const float* Wq    = (const float*)d_in[3];
    const float* bq    = (const float*)d_in[4];
    const float* Wk    = (const float*)d_in[5];
    const float* bk    = (const float*)d_in[6];
    const float* Wv    = (const float*)d_in[7];
    const float* bv    = (const float*)d_in[8];
    const float* Wo    = (const float*)d_in[9];
    const float* bo    = (const float*)d_in[10];
    const float* Wp    = (const float*)d_in[11];
    const float* pbu   = (const float*)d_in[12];
    const float* pbv   = (const float*)d_in[13];
    const float* ln1s  = (const float*)d_in[14];
    const float* ln1b  = (const float*)d_in[15];
    const float* ln2s  = (const float*)d_in[16];
    const float* ln2b  = (const float*)d_in[17];
    const float* W1    = (const float*)d_in[18];
    const float* b1    = (const float*)d_in[19];
    const float* W2    = (const float*)d_in[20];
    const float* b2    = (const float*)d_in[21];
    const float* lnfs  = (const float*)d_in[22];
    const float* lnfb  = (const float*)d_in[23];

    cudaFuncSetAttribute(attn_kernel, cudaFuncAttributeMaxDynamicSharedMemorySize, ATTN_SMEM);
    cudaFuncSetAttribute(gemm_h3,     cudaFuncAttributeMaxDynamicSharedMemorySize, GEMM_SMEM);

    void* a;
    #define SYM(p, s) cudaGetSymbolAddress(&a, s); auto* p = (decltype(&s[0]))a;
    SYM(px, g_x)  SYM(pqkv, g_qkv)  SYM(ppall, g_pall)  SYM(pbqkv, g_bqkv)
    SYM(phh, g_hh) SYM(phl, g_hl)
    SYM(poh, g_oh) SYM(pol, g_ol)
    SYM(pffh, g_ffh) SYM(pffl, g_ffl)
    SYM(pposh, g_posh) SYM(pposl, g_posl)
    SYM(pwqkvh, g_wqkvh) SYM(pwqkvl, g_wqkvl)
    SYM(pwoh, g_woh) SYM(pwol, g_wol)
    SYM(pwph, g_wph) SYM(pwpl, g_wpl)
    SYM(pw1h, g_w1h) SYM(pw1l, g_w1l)
    SYM(pw2h, g_w2h) SYM(pw2l, g_w2l)
    #undef SYM

    const int M = B_ * T_;  // 4096
    const size_t DD = (size_t)D_ * D_;          // 262144
    const size_t QKVLS = (size_t)QKVN_ * D_;    // 786432

    // prep: x scale, pos split, bias concat, weight transpose+split
    scale_kernel<<<(B_*T_*D_) / 256, 256>>>(xs, sqrtf((float)D_));
    posconv_kernel<<<(T_*D_) / 256, 256>>>(pos);
    bcat_kernel<<<(L_*QKVN_) / 256, 256>>>(bq, bk, bv);
    dim3 wtb(32, 8);
    wtrans_kernel<<<dim3(D_/32,  D_/32,  L_), wtb>>>(Wq, pwqkvh,          pwqkvl,          D_, D_, DD, QKVLS);
    wtrans_kernel<<<dim3(D_/32,  D_/32,  L_), wtb>>>(Wk, pwqkvh + DD,     pwqkvl + DD,     D_, D_, DD, QKVLS);
    wtrans_kernel<<<dim3(D_/32,  D_/32,  L_), wtb>>>(Wv, pwqkvh + 2*DD,   pwqkvl + 2*DD,   D_, D_, DD, QKVLS);
    wtrans_kernel<<<dim3(D_/32,  D_/32,  L_), wtb>>>(Wo, pwoh, pwol, D_,  D_,  DD, DD);
    wtrans_kernel<<<dim3(D_/32,  D_/32,  L_), wtb>>>(Wp, pwph, pwpl, D_,  D_,  DD, DD);
    wtrans_kernel<<<dim3(FF_/32, D_/32,  L_), wtb>>>(W1, pw1h, pw1l, D_,  FF_, (size_t)D_*FF_, (size_t)D_*FF_);
    wtrans_kernel<<<dim3(D_/32,  FF_/32, L_), wtb>>>(W2, pw2h, pw2l, FF_, D_,  (size_t)FF_*D_, (size_t)FF_*D_);

    // p_all = pos_emb @ Wp (all 6 layers in one GEMM, N = L*D = 3072)
    gemm_h3<<<dim3(PALLN_/128, T_/128), 256, GEMM_SMEM>>>(pposh, pposl, pwph, pwpl,
        nullptr, nullptr, ppall, nullptr, nullptr, PALLN_, D_, 0);

    for (int l = 0; l < L_; l++) {
        size_t wdf = (size_t)l * D_ * FF_;

        // h = LN1(x)  (fp16 hi/lo)
        ln_h3_kernel<<<M, 256>>>(px, phh, phl, ln1s + l * D_, ln1b + l * D_);

        // qkv = h @ [Wq|Wk|Wv] + [bq|bk|bv]   (fused, fp32 out)
        gemm_h3<<<dim3(QKVN_/128, M/128), 256, GEMM_SMEM>>>(phh, phl,
            pwqkvh + l * QKVLS, pwqkvl + l * QKVLS,
            pbqkv + l * QKVN_, nullptr, pqkv, nullptr, nullptr, QKVN_, D_, 0);

        // attention (chunked local) -> o hi/lo
        attn_kernel<<<dim3(NCHUNK_, H_, B_), 256, ATTN_SMEM>>>(
            pqkv, ppall + l * D_, pbu + l * H_ * DK_, pbv + l * H_ * DK_, poh, pol);

        // x = x + o @ Wo + bo
        gemm_h3<<<dim3(D_/128, M/128), 256, GEMM_SMEM>>>(poh, pol,
            pwoh + l * DD, pwol + l * DD,
            bo + l*D_, px, px, nullptr, nullptr, D_, D_, 0);

        // h2 = LN2(x)  (fp16 hi/lo)
        ln_h3_kernel<<<M, 256>>>(px, phh, phl, ln2s + l * D_, ln2b + l * D_);

        // ff = relu(h2 @ W1 + b1)  (fp16 hi/lo out only)
        gemm_h3<<<dim3(FF_/128, M/128), 256, GEMM_SMEM>>>(phh, phl,
            pw1h + wdf, pw1l + wdf,
            b1 + l*FF_, nullptr, nullptr, pffh, pffl, FF_, D_, 1);

        // x = x + ff @ W2 + b2
        gemm_h3<<<dim3(D_/128, M/128), 256, GEMM_SMEM>>>(pffh, pffl,
            pw2h + wdf, pw2l + wdf,
            b2 + l*D_, px, px, nullptr, nullptr, D_, FF_, 0);
    }

    // out = LNf(x)  (fp32)
    ln_kernel<<<M, 256>>>(px, (float*)d_out, lnfs, lnfb);
}

// round 6
// speedup vs baseline: 2.5088x; 1.0233x over previous
#include <cuda_runtime.h>
#include <cuda_fp16.h>
#include <math.h>
#include <stdint.h>

// Problem constants
#define B_  8
#define T_  512
#define D_  512
#define H_  8
#define FF_ 2048
#define L_  6
#define CS_ 16
#define LC_ 4
#define DK_ 64
#define NCHUNK_ (T_ / CS_)          // 32
#define WMAX_ ((LC_ + 1) * CS_)     // 80
#define QKVN_ (3 * D_)              // 1536
#define PALLN_ (L_ * D_)            // 3072

// ---------------- scratch (device globals; no allocation) ----------------
__device__ float  g_x   [B_*T_*D_];
__device__ float  g_qkv [B_*T_*QKVN_];
__device__ float  g_o   [B_*T_*D_];
__device__ float  g_ff  [B_*T_*FF_];
__device__ float  g_pall[T_*PALLN_];
__device__ float  g_bqkv[L_*QKVN_];
__device__ float2 g_st  [B_*T_];

// transposed + split weights: Wt[n][k]
__device__ __half g_wqkvh[L_*QKVN_*D_], g_wqkvl[L_*QKVN_*D_];
__device__ __half g_woh[L_*D_*D_],  g_wol[L_*D_*D_];
__device__ __half g_wph[L_*D_*D_],  g_wpl[L_*D_*D_];
__device__ __half g_w1h[L_*D_*FF_], g_w1l[L_*D_*FF_];
__device__ __half g_w2h[L_*FF_*D_], g_w2l[L_*FF_*D_];

// ---------------- PTX helpers (family-portable: sm_80+ ISA only) ----------
__device__ __forceinline__ uint32_t s2u(const void* p) {
    uint32_t a;
    asm("{ .reg .u64 t; cvta.to.shared.u64 t, %1; cvt.u32.u64 %0, t; }" : "=r"(a) : "l"(p));
    return a;
}

#define CPA16(sa, g) \
    asm volatile("cp.async.cg.shared.global [%0], [%1], 16;" :: "r"(sa), "l"(g) : "memory")
#define CPCOMMIT() asm volatile("cp.async.commit_group;" ::: "memory")
#define CPWAIT(n)  asm volatile("cp.async.wait_group %0;" :: "n"(n) : "memory")

#define LDSM4(d0, d1, d2, d3, a) \
    asm volatile("ldmatrix.sync.aligned.m8n8.x4.shared.b16 {%0,%1,%2,%3}, [%4];" \
        : "=r"(d0), "=r"(d1), "=r"(d2), "=r"(d3) : "r"(a))

#define MMA16816(c, a, b0, b1) \
    asm volatile("mma.sync.aligned.m16n8k16.row.col.f32.f16.f16.f32 " \
        "{%0,%1,%2,%3}, {%4,%5,%6,%7}, {%8,%9}, {%0,%1,%2,%3};" \
        : "+f"((c)[0]), "+f"((c)[1]), "+f"((c)[2]), "+f"((c)[3]) \
        : "r"((a)[0]), "r"((a)[1]), "r"((a)[2]), "r"((a)[3]), "r"(b0), "r"(b1))

#define SWZ(o) ((o) ^ (((o) >> 3) & 0x30))   // unused for 64B rows; keep chunk xor below

__device__ __forceinline__ void split_h(float v, __half& hi, __half& lo) {
    hi = __float2half_rn(v);
    lo = __float2half_rn(v - __half2float(hi));
}
__device__ __forceinline__ uint32_t pack2(__half a, __half b) {
    __half2 t = __halves2half2(a, b);
    return *reinterpret_cast<uint32_t*>(&t);
}
__device__ __forceinline__ float4 ld4h(const __half* p) {
    uint2 u = *(const uint2*)p;
    __half2 a = *reinterpret_cast<__half2*>(&u.x);
    __half2 b = *reinterpret_cast<__half2*>(&u.y);
    float2 fa = __half22float2(a), fb = __half22float2(b);
    return make_float4(fa.x, fa.y, fb.x, fb.y);
}
__device__ __forceinline__ float dot4(float4 a, float4 b) {
    return a.x * b.x + a.y * b.y + a.z * b.z + a.w * b.w;
}

// ---------------- elementwise scale: x = xs * sqrt(D) ----------------
__global__ void scale_kernel(const float* __restrict__ xs, float s) {
    int i = blockIdx.x * blockDim.x + threadIdx.x;
    g_x[i] = xs[i] * s;
}

// ---------------- bias concat for fused QKV ----------------
__global__ void bcat_kernel(const float* __restrict__ bq, const float* __restrict__ bk,
                            const float* __restrict__ bv) {
    int i = blockIdx.x * blockDim.x + threadIdx.x;   // L*1536
    int l = i / QKVN_, c = i % QKVN_;
    float v = (c < D_) ? bq[l * D_ + c]
            : (c < 2 * D_) ? bk[l * D_ + c - D_]
            : bv[l * D_ + c - 2 * D_];
    g_bqkv[i] = v;
}

// ---------------- weight transpose + split: W[K][N] -> Wt_hi/lo[N][K] ------
__global__ void wtrans_kernel(const float* __restrict__ W,
                              __half* __restrict__ Th, __half* __restrict__ Tl,
                              int K, int N, size_t srcLS, size_t dstLS) {
    __shared__ float sm[32][33];
    const float* Wl = W + (size_t)blockIdx.z * srcLS;
    __half* Thl = Th + (size_t)blockIdx.z * dstLS;
    __half* Tll = Tl + (size_t)blockIdx.z * dstLS;
    int n0 = blockIdx.x * 32, k0 = blockIdx.y * 32;
    int tx = threadIdx.x, ty = threadIdx.y;
    #pragma unroll
    for (int j = 0; j < 4; j++)
        sm[ty + j * 8][tx] = Wl[(size_t)(k0 + ty + j * 8) * N + n0 + tx];
    __syncthreads();
    #pragma unroll
    for (int j = 0; j < 4; j++) {
        int n = ty + j * 8;
        float v = sm[tx][n];
        __half h, l;
        split_h(v, h, l);
        size_t o = (size_t)(n0 + n) * K + k0 + tx;
        Thl[o] = h; Tll[o] = l;
    }
}

// ---------------- LayerNorm stats / final LN ----------------
__device__ __forceinline__ void ln_stats(const float* x, int tid, float& v0, float& v1,
                                         float& mean, float& inv, float* sh_s, float* sh_ss) {
    v0 = x[tid]; v1 = x[tid + 256];
    float s = v0 + v1, ss = v0 * v0 + v1 * v1;
    int lane = tid & 31, warp = tid >> 5;
    #pragma unroll
    for (int off = 16; off; off >>= 1) {
        s  += __shfl_xor_sync(0xffffffffu, s,  off);
        ss += __shfl_xor_sync(0xffffffffu, ss, off);
    }
    if (lane == 0) { sh_s[warp] = s; sh_ss[warp] = ss; }
    __syncthreads();
    if (warp == 0) {
        float a = (lane < 8) ? sh_s[lane]  : 0.0f;
        float b = (lane < 8) ? sh_ss[lane] : 0.0f;
        #pragma unroll
        for (int off = 4; off; off >>= 1) {
            a += __shfl_xor_sync(0xffffffffu, a, off);
            b += __shfl_xor_sync(0xffffffffu, b, off);
        }
        if (lane == 0) { sh_s[0] = a; sh_ss[0] = b; }
    }
    __syncthreads();
    mean = sh_s[0] * (1.0f / D_);
    float var = sh_ss[0] * (1.0f / D_) - mean * mean;
    inv = rsqrtf(var + 1e-5f);
}

__global__ void lnstats_kernel(const float* __restrict__ in, float2* __restrict__ st) {
    __shared__ float sh_s[8], sh_ss[8];
    int row = blockIdx.x, tid = threadIdx.x;
    float v0, v1, mean, inv;
    ln_stats(in + (size_t)row * D_, tid, v0, v1, mean, inv, sh_s, sh_ss);
    if (tid == 0) st[row] = make_float2(mean, inv);
}

__global__ void ln_kernel(const float* __restrict__ in, float* __restrict__ out,
                          const float* __restrict__ gam, const float* __restrict__ bet) {
    __shared__ float sh_s[8], sh_ss[8];
    int row = blockIdx.x, tid = threadIdx.x;
    const float* x = in + (size_t)row * D_;
    float v0, v1, mean, inv;
    ln_stats(x, tid, v0, v1, mean, inv, sh_s, sh_ss);
    float* y = out + (size_t)row * D_;
    y[tid]       = (v0 - mean) * inv * gam[tid]       + bet[tid];
    y[tid + 256] = (v1 - mean) * inv * gam[tid + 256] + bet[tid + 256];
}

// ---------------- HMMA fp16x3 GEMM, fp32-A with fused LN/convert -----------
// C[M x N] = A[M x K] @ W[K x N]. A is fp32 (optionally LayerNorm'd on the
// fly using per-row (mean,inv) stats + gamma/beta), split to fp16 hi/lo in
// the loader (LDG -> STS). W pre-transposed Bt[N][K] fp16 hi/lo via cp.async.
// Block 128x128x32, 8 warps, warp tile 64x32, 2-stage pipeline.
#define STAGE_BYTES 32768
__global__ void __launch_bounds__(256, 2)
gemm_f32a(const float* __restrict__ A, const float2* __restrict__ stats,
          const float* __restrict__ gam, const float* __restrict__ bet,
          const __half* __restrict__ Bh, const __half* __restrict__ Bl,
          const float* __restrict__ bias, const float* __restrict__ res,
          float* __restrict__ outF, int N, int K, int relu) {
    extern __shared__ char smem[];
    uint32_t sb = s2u(smem);
    int tid = threadIdx.x, lane = tid & 31, wid = tid >> 5;
    int wm = wid >> 2, wn = wid & 3;
    int rowBase = blockIdx.y * 128, colBase = blockIdx.x * 128;
    int sub = lane & 7, grp = lane >> 3;

    float acc[4][4][4];
    #pragma unroll
    for (int i = 0; i < 4; i++)
        #pragma unroll
        for (int j = 0; j < 4; j++)
            #pragma unroll
            for (int c = 0; c < 4; c++) acc[i][j][c] = 0.0f;

    const int NC = K >> 5;

    // per-thread A chunk coords (fixed across stages)
    float aR[2][8];
    float2 stR[2];
    #pragma unroll
    for (int i = 0; i < 2; i++) {
        int id = tid + (i << 8);
        int row = id >> 2;
        stR[i] = stats ? stats[rowBase + row] : make_float2(0.0f, 1.0f);
    }

    auto ldgA = [&](int c) {
        int k0 = c << 5;
        #pragma unroll
        for (int i = 0; i < 2; i++) {
            int id = tid + (i << 8);
            int row = id >> 2, ch = id & 3;
            const float* g = A + (size_t)(rowBase + row) * K + k0 + ch * 8;
            float4 u = *(const float4*)g;
            float4 v = *(const float4*)(g + 4);
            aR[i][0] = u.x; aR[i][1] = u.y; aR[i][2] = u.z; aR[i][3] = u.w;
            aR[i][4] = v.x; aR[i][5] = v.y; aR[i][6] = v.z; aR[i][7] = v.w;
        }
    };

    auto stsA = [&](int c, int buf) {
        int k0 = c << 5;
        #pragma unroll
        for (int i = 0; i < 2; i++) {
            int id = tid + (i << 8);
            int row = id >> 2, ch = id & 3;
            float y[8];
            if (gam) {
                float mean = stR[i].x, inv = stR[i].y;
                const float* gg = gam + k0 + ch * 8;
                const float* bb = bet + k0 + ch * 8;
                float4 g0 = *(const float4*)gg, g1 = *(const float4*)(gg + 4);
                float4 b0 = *(const float4*)bb, b1 = *(const float4*)(bb + 4);
                y[0] = (aR[i][0] - mean) * inv * g0.x + b0.x;
                y[1] = (aR[i][1] - mean) * inv * g0.y + b0.y;
                y[2] = (aR[i][2] - mean) * inv * g0.z + b0.z;
                y[3] = (aR[i][3] - mean) * inv * g0.w + b0.w;
                y[4] = (aR[i][4] - mean) * inv * g1.x + b1.x;
                y[5] = (aR[i][5] - mean) * inv * g1.y + b1.y;
                y[6] = (aR[i][6] - mean) * inv * g1.z + b1.z;
                y[7] = (aR[i][7] - mean) * inv * g1.w + b1.w;
            } else {
                #pragma unroll
                for (int j = 0; j < 8; j++) y[j] = aR[i][j];
            }
            __half h[8], l[8];
            #pragma unroll
            for (int j = 0; j < 8; j++) split_h(y[j], h[j], l[j]);
            int phys = ch ^ ((row >> 1) & 3);
            uint32_t rel = (uint32_t)(buf * STAGE_BYTES) + row * 64 + phys * 16;
            uint4 wh, wl;
            wh.x = pack2(h[0], h[1]); wh.y = pack2(h[2], h[3]);
            wh.z = pack2(h[4], h[5]); wh.w = pack2(h[6], h[7]);
            wl.x = pack2(l[0], l[1]); wl.y = pack2(l[2], l[3]);
            wl.z = pack2(l[4], l[5]); wl.w = pack2(l[6], l[7]);
            *(uint4*)(smem + rel)         = wh;
            *(uint4*)(smem + rel + 8192u) = wl;
        }
    };

    auto loadB = [&](int c, int buf) {
        uint32_t sbase = sb + buf * STAGE_BYTES + 16384u;
        int k0 = c << 5;
        #pragma unroll
        for (int i = 0; i < 2; i++) {
            int id = tid + (i << 8);
            int row = id >> 2, ch = id & 3;
            int phys = ch ^ ((row >> 1) & 3);
            uint32_t so = sbase + row * 64 + phys * 16;
            CPA16(so,          Bh + (size_t)(colBase + row) * K + k0 + ch * 8);
            CPA16(so + 8192u,  Bl + (size_t)(colBase + row) * K + k0 + ch * 8);
        }
    };

    auto compute = [&](int buf) {
        uint32_t base = sb + buf * STAGE_BYTES;
        #pragma unroll
        for (int ks = 0; ks < 2; ks++) {
            uint32_t ahf[4][4], alf[4][4], bhf[4][2], blf[4][2];
            #pragma unroll
            for (int mi = 0; mi < 4; mi++) {
                int row = wm * 64 + mi * 16 + sub + (grp & 1) * 8;
                int ci = 2 * ks + (grp >> 1);
                uint32_t ad = base + row * 64 + ((ci ^ ((row >> 1) & 3)) * 16);
                LDSM4(ahf[mi][0], ahf[mi][1], ahf[mi][2], ahf[mi][3], ad);
                LDSM4(alf[mi][0], alf[mi][1], alf[mi][2], alf[mi][3], ad + 8192u);
            }
            #pragma unroll
            for (int g = 0; g < 2; g++) {
                int row = wn * 32 + g * 16 + sub + (grp & 1) * 8;
                int ci = 2 * ks + (grp >> 1);
                uint32_t ad = base + 16384u + row * 64 + ((ci ^ ((row >> 1) & 3)) * 16);
                uint32_t r0, r1, r2, r3;
                LDSM4(r0, r1, r2, r3, ad);
                bhf[2*g][0] = r0; bhf[2*g+1][0] = r1; bhf[2*g][1] = r2; bhf[2*g+1][1] = r3;
                LDSM4(r0, r1, r2, r3, ad + 8192u);
                blf[2*g][0] = r0; blf[2*g+1][0] = r1; blf[2*g][1] = r2; blf[2*g+1][1] = r3;
            }
            #pragma unroll
            for (int mi = 0; mi < 4; mi++)
                #pragma unroll
                for (int nj = 0; nj < 4; nj++)
                    MMA16816(acc[mi][nj], ahf[mi], bhf[nj][0], bhf[nj][1]);
            #pragma unroll
            for (int mi = 0; mi < 4; mi++)
                #pragma unroll
                for (int nj = 0; nj < 4; nj++)
                    MMA16816(acc[mi][nj], ahf[mi], blf[nj][0], blf[nj][1]);
            #pragma unroll
            for (int mi = 0; mi < 4; mi++)
                #pragma unroll
                for (int nj = 0; nj < 4; nj++)
                    MMA16816(acc[mi][nj], alf[mi], bhf[nj][0], bhf[nj][1]);
        }
    };

    // prologue
    ldgA(0);
    stsA(0, 0);
    loadB(0, 0);
    CPCOMMIT();
    #pragma unroll 1
    for (int c = 0; c < NC; c++) {
        if (c + 1 < NC) ldgA(c + 1);       // LDG in flight over the B-wait
        CPWAIT(0);
        __syncthreads();
        if (c + 1 < NC) loadB(c + 1, (c + 1) & 1);
        CPCOMMIT();
        if (c + 1 < NC) stsA(c + 1, (c + 1) & 1);
        compute(c & 1);
    }

    // --- epilogue (fp32 out only) ---
    #pragma unroll
    for (int mi = 0; mi < 4; mi++) {
        #pragma unroll
        for (int nj = 0; nj < 4; nj++) {
            int r = rowBase + wm * 64 + mi * 16 + (lane >> 2);
            int c = colBase + wn * 32 + nj * 8 + ((lane & 3) << 1);
            #pragma unroll
            for (int half_ : {0, 1}) {
                int rr = r + half_ * 8;
                float v0 = acc[mi][nj][half_ * 2 + 0];
                float v1 = acc[mi][nj][half_ * 2 + 1];
                if (bias) { v0 += bias[c]; v1 += bias[c + 1]; }
                if (res) {
                    float2 rv = *(const float2*)(res + (size_t)rr * N + c);
                    v0 += rv.x; v1 += rv.y;
                }
                if (relu) { v0 = fmaxf(v0, 0.0f); v1 = fmaxf(v1, 0.0f); }
                *(float2*)(outF + (size_t)rr * N + c) = make_float2(v0, v1);
            }
        }
    }
}

// ---------------- Chunked local attention (fp16 scores path, fp32 out) -----
__global__ void attn_kernel(const float* __restrict__ qkv, const float* __restrict__ p,
                            const float* __restrict__ pbu, const float* __restrict__ pbv,
                            float* __restrict__ o) {
    int ci = blockIdx.x, h = blockIdx.y, b = blockIdx.z;
    int s0 = max((ci - LC_) * CS_, 0);
    int s1 = (ci + 1) * CS_;
    int W = s1 - s0;
    int t0 = ci * CS_;
    int tid = threadIdx.x;                    // 256 threads

    extern __shared__ char asmem[];
    __half* Ks = (__half*)asmem;              // WMAX*64 halves
    __half* Ps = Ks + WMAX_ * 64;
    __half* QU = Ps + WMAX_ * 64;             // 16*64
    __half* QV = QU + 16 * 64;
    float* Vs = (float*)(QV + 16 * 64);       // WMAX*64 floats
    float* SC = Vs + WMAX_ * 64;              // 16*WMAX

    for (int idx = tid; idx < W * 64; idx += 256) {
        int s = idx >> 6, d = idx & 63;
        size_t gi = (size_t)((b * T_) + s0 + s) * QKVN_ + h * DK_ + d;
        Ks[idx] = __float2half(qkv[gi + D_]);
        Vs[idx] = qkv[gi + 2 * D_];
        Ps[idx] = __float2half(p[(size_t)(s0 + s) * PALLN_ + h * DK_ + d]);
    }
    for (int idx = tid; idx < 16 * 64; idx += 256) {
        int qi = idx >> 6, d = idx & 63;
        float qv_ = qkv[(size_t)((b * T_) + t0 + qi) * QKVN_ + h * DK_ + d];
        QU[idx] = __float2half(qv_ + pbu[h * DK_ + d]);
        QV[idx] = __float2half(qv_ + pbv[h * DK_ + d]);
    }
    __syncthreads();

    const float scale = 0.125f;
    int Wh = W >> 1;
    for (int it = tid; it < 8 * Wh; it += 256) {
        int qi = (it / Wh) * 2, s = (it % Wh) * 2;
        float a00 = 0, a01 = 0, a10 = 0, a11 = 0;
        #pragma unroll 4
        for (int d = 0; d < 64; d += 4) {
            float4 qu0 = ld4h(&QU[qi * 64 + d]);
            float4 qu1 = ld4h(&QU[(qi + 1) * 64 + d]);
            float4 qv0 = ld4h(&QV[qi * 64 + d]);
            float4 qv1 = ld4h(&QV[(qi + 1) * 64 + d]);
            float4 k0 = ld4h(&Ks[s * 64 + d]);
            float4 k1 = ld4h(&Ks[(s + 1) * 64 + d]);
            float4 p0 = ld4h(&Ps[s * 64 + d]);
            float4 p1 = ld4h(&Ps[(s + 1) * 64 + d]);
            a00 += dot4(qu0, k0) + dot4(qv0, p0);
            a01 += dot4(qu0, k1) + dot4(qv0, p1);
            a10 += dot4(qu1, k0) + dot4(qv1, p0);
            a11 += dot4(qu1, k1) + dot4(qv1, p1);
        }
        SC[qi * WMAX_ + s]           = a00 * scale;
        SC[qi * WMAX_ + s + 1]       = a01 * scale;
        SC[(qi + 1) * WMAX_ + s]     = a10 * scale;
        SC[(qi + 1) * WMAX_ + s + 1] = a11 * scale;
    }
    __syncthreads();

    int warp = tid >> 5, lane = tid & 31;
    for (int qi = warp; qi < 16; qi += 8) {
        float m = -1e30f;
        for (int s = lane; s < W; s += 32) m = fmaxf(m, SC[qi * WMAX_ + s]);
        #pragma unroll
        for (int off = 16; off; off >>= 1) m = fmaxf(m, __shfl_xor_sync(0xffffffffu, m, off));
        float sum = 0.0f;
        for (int s = lane; s < W; s += 32) {
            float e = expf(SC[qi * WMAX_ + s] - m);
            SC[qi * WMAX_ + s] = e;
            sum += e;
        }
        #pragma unroll
        for (int off = 16; off; off >>= 1) sum += __shfl_xor_sync(0xffffffffu, sum, off);
        float inv = 1.0f / sum;
        for (int s = lane; s < W; s += 32) SC[qi * WMAX_ + s] *= inv;
    }
    __syncthreads();

    // A @ V: 2-qi x 2-d blocking, fp32 V
    {
        int it = tid;                       // 8 * 32 = 256
        int qi = (it >> 5) * 2, d = (it & 31) * 2;
        float a00 = 0, a01 = 0, a10 = 0, a11 = 0;
        for (int s = 0; s < W; s++) {
            float2 vv = *(const float2*)&Vs[s * 64 + d];
            float c0 = SC[qi * WMAX_ + s];
            float c1 = SC[(qi + 1) * WMAX_ + s];
            a00 += c0 * vv.x; a01 += c0 * vv.y;
            a10 += c1 * vv.x; a11 += c1 * vv.y;
        }
        size_t o0 = (size_t)((b * T_) + t0 + qi) * D_ + h * DK_ + d;
        *(float2*)(o + o0)      = make_float2(a00, a01);
        *(float2*)(o + o0 + D_) = make_float2(a10, a11);
    }
}

static const int ATTN_SMEM = (WMAX_*64*2 + 16*64*2) * 2 + (WMAX_*64 + 16*WMAX_) * 4; // 50176
static const int GEMM_SMEM = 2 * STAGE_BYTES;   // 65536

extern "C" void kernel_launch(void* const* d_in, const int* in_sizes, int n_in,
                              void* d_out, int out_size) {
    (void)in_sizes; (void)n_in; (void)out_size;
    const float* xs    = (const float*)d_in[0];
    const float* pos   = (const float*)d_in[1];
    // d_in[2] = mask: unused (window computed analytically)
    const float* Wq    = (const float*)d_in[3];
    const float* bq    = (const float*)d_in[4];
    const float* Wk    = (const float*)d_in[5];
    const float* bk    = (const float*)d_in[6];
    const float* Wv    = (const float*)d_in[7];
    const float* bv    = (const float*)d_in[8];
    const float* Wo    = (const float*)d_in[9];
    const float* bo    = (const float*)d_in[10];
    const float* Wp    = (const float*)d_in[11];
    const float* pbu   = (const float*)d_in[12];
    const float* pbv   = (const float*)d_in[13];
    const float* ln1s  = (const float*)d_in[14];
    const float* ln1b  = (const float*)d_in[15];
    const float* ln2s  = (const float*)d_in[16];
    const float* ln2b  = (const float*)d_in[17];
    const float* W1    = (const float*)d_in[18];
    const float* b1    = (const float*)d_in[19];
    const float* W2    = (const float*)d_in[20];
    const float* b2    = (const float*)d_in[21];
    const float* lnfs  = (const float*)d_in[22];
    const float* lnfb  = (const float*)d_in[23];

    cudaFuncSetAttribute(attn_kernel, cudaFuncAttributeMaxDynamicSharedMemorySize, ATTN_SMEM);
    cudaFuncSetAttribute(gemm_f32a,   cudaFuncAttributeMaxDynamicSharedMemorySize, GEMM_SMEM);

    void* a;
    #define SYM(p, s) cudaGetSymbolAddress(&a, s); auto* p = (decltype(&s[0]))a;
    SYM(px, g_x)  SYM(pqkv, g_qkv)  SYM(po, g_o)  SYM(pff, g_ff)
    SYM(ppall, g_pall)  SYM(pbqkv, g_bqkv)  SYM(pst, g_st)
    SYM(pwqkvh, g_wqkvh) SYM(pwqkvl, g_wqkvl)
    SYM(pwoh, g_woh) SYM(pwol, g_wol)
    SYM(pwph, g_wph) SYM(pwpl, g_wpl)
    SYM(pw1h, g_w1h) SYM(pw1l, g_w1l)
    SYM(pw2h, g_w2h) SYM(pw2l, g_w2l)
    #undef SYM

    const int M = B_ * T_;  // 4096
    const size_t DD = (size_t)D_ * D_;          // 262144
    const size_t QKVLS = (size_t)QKVN_ * D_;    // 786432

    // prep
    scale_kernel<<<(B_*T_*D_) / 256, 256>>>(xs, sqrtf((float)D_));
    bcat_kernel<<<(L_*QKVN_) / 256, 256>>>(bq, bk, bv);
    dim3 wtb(32, 8);
    wtrans_kernel<<<dim3(D_/32,  D_/32,  L_), wtb>>>(Wq, pwqkvh,        pwqkvl,        D_, D_, DD, QKVLS);
    wtrans_kernel<<<dim3(D_/32,  D_/32,  L_), wtb>>>(Wk, pwqkvh + DD,   pwqkvl + DD,   D_, D_, DD, QKVLS);
    wtrans_kernel<<<dim3(D_/32,  D_/32,  L_), wtb>>>(Wv, pwqkvh + 2*DD, pwqkvl + 2*DD, D_, D_, DD, QKVLS);
    wtrans_kernel<<<dim3(D_/32,  D_/32,  L_), wtb>>>(Wo, pwoh, pwol, D_,  D_,  DD, DD);
    wtrans_kernel<<<dim3(D_/32,  D_/32,  L_), wtb>>>(Wp, pwph, pwpl, D_,  D_,  DD, DD);
    wtrans_kernel<<<dim3(FF_/32, D_/32,  L_), wtb>>>(W1, pw1h, pw1l, D_,  FF_, (size_t)D_*FF_, (size_t)D_*FF_);
    wtrans_kernel<<<dim3(D_/32,  FF_/32, L_), wtb>>>(W2, pw2h, pw2l, FF_, D_,  (size_t)FF_*D_, (size_t)FF_*D_);

    // p_all = pos_emb @ Wp (all 6 layers, fp32 A loader, no LN)
    gemm_f32a<<<dim3(PALLN_/128, T_/128), 256, GEMM_SMEM>>>(pos, nullptr, nullptr, nullptr,
        pwph, pwpl, nullptr, nullptr, ppall, PALLN_, D_, 0);

    for (int l = 0; l < L_; l++) {
        size_t wdf = (size_t)l * D_ * FF_;

        // row stats for LN1
        lnstats_kernel<<<M, 256>>>(px, pst);

        // qkv = LN1(x) @ [Wq|Wk|Wv] + b  (LN fused into A loader)
        gemm_f32a<<<dim3(QKVN_/128, M/128), 256, GEMM_SMEM>>>(px, pst,
            ln1s + l*D_, ln1b + l*D_,
            pwqkvh + l * QKVLS, pwqkvl + l * QKVLS,
            pbqkv + l * QKVN_, nullptr, pqkv, QKVN_, D_, 0);

        // attention -> o fp32
        attn_kernel<<<dim3(NCHUNK_, H_, B_), 256, ATTN_SMEM>>>(
            pqkv, ppall + l * D_, pbu + l * H_ * DK_, pbv + l * H_ * DK_, po);

        // x = x + o @ Wo + bo
        gemm_f32a<<<dim3(D_/128, M/128), 256, GEMM_SMEM>>>(po, nullptr, nullptr, nullptr,
            pwoh + l * DD, pwol + l * DD,
            bo + l*D_, px, px, D_, D_, 0);

        // row stats for LN2
        lnstats_kernel<<<M, 256>>>(px, pst);

        // ff = relu(LN2(x) @ W1 + b1)  (fp32 out)
        gemm_f32a<<<dim3(FF_/128, M/128), 256, GEMM_SMEM>>>(px, pst,
            ln2s + l*D_, ln2b + l*D_,
            pw1h + wdf, pw1l + wdf,
            b1 + l*FF_, nullptr, pff, FF_, D_, 1);

        // x = x + ff @ W2 + b2
        gemm_f32a<<<dim3(D_/128, M/128), 256, GEMM_SMEM>>>(pff, nullptr, nullptr, nullptr,
            pw2h + wdf, pw2l + wdf,
            b2 + l*D_, px, px, D_, FF_, 0);
    }

    // out = LNf(x)  (fp32)
    ln_kernel<<<M, 256>>>(px, (float*)d_out, lnfs, lnfb);
}